// round 2
// baseline (speedup 1.0000x reference)
#include <cuda_runtime.h>
#include <math.h>

#define DIMM   2048
#define NHEAD  16
#define HDIM   128
#define SEQ    2048
#define BATCH  2
#define MTOK   (BATCH*SEQ)   // 4096 tokens

// Scratch (device globals; no allocation allowed)
__device__ float g_Q[(size_t)MTOK * DIMM];
__device__ float g_K[(size_t)MTOK * DIMM];
__device__ float g_V[(size_t)MTOK * DIMM];
__device__ float g_A[(size_t)MTOK * DIMM];

// ---------------------------------------------------------------------------
// SGEMM with bias: C[M,N] = A[M,K] @ B[K,N] + bias[N]
// 128x128 block tile, BK=8, 256 threads, 8x8 register micro-tile.
// ---------------------------------------------------------------------------
#define GBM 128
#define GBN 128
#define GBK 8

__global__ __launch_bounds__(256) void sgemm_bias(
    const float* __restrict__ A, const float* __restrict__ B,
    const float* __restrict__ bias, float* __restrict__ C,
    int M, int N, int K)
{
    __shared__ float As[GBK][GBM];   // A transposed: As[k][m]
    __shared__ float Bs[GBK][GBN];   // B row-major:  Bs[k][n]

    const int tid = threadIdx.x;
    const int tx  = tid & 15;        // n direction (16)
    const int ty  = tid >> 4;        // m direction (16)
    const int bm  = blockIdx.y * GBM;
    const int bn  = blockIdx.x * GBN;

    float acc[8][8];
#pragma unroll
    for (int i = 0; i < 8; i++)
#pragma unroll
        for (int j = 0; j < 8; j++) acc[i][j] = 0.0f;

    const int a_row = tid >> 1;          // 0..127
    const int a_col = (tid & 1) * 4;     // 0 or 4
    const int b_row = tid >> 5;          // 0..7
    const int b_col = (tid & 31) * 4;    // 0..124

    const float* Ap = A + (size_t)(bm + a_row) * K + a_col;
    const float* Bp = B + (size_t)b_row * N + bn + b_col;

    for (int k0 = 0; k0 < K; k0 += GBK) {
        float4 av = *(const float4*)(Ap + k0);
        As[a_col + 0][a_row] = av.x;
        As[a_col + 1][a_row] = av.y;
        As[a_col + 2][a_row] = av.z;
        As[a_col + 3][a_row] = av.w;
        *(float4*)&Bs[b_row][b_col] = *(const float4*)(Bp + (size_t)k0 * N);
        __syncthreads();

#pragma unroll
        for (int kk = 0; kk < GBK; kk++) {
            float a[8], b[8];
            *(float4*)&a[0] = *(const float4*)&As[kk][ty * 8];
            *(float4*)&a[4] = *(const float4*)&As[kk][ty * 8 + 4];
            *(float4*)&b[0] = *(const float4*)&Bs[kk][tx * 8];
            *(float4*)&b[4] = *(const float4*)&Bs[kk][tx * 8 + 4];
#pragma unroll
            for (int i = 0; i < 8; i++)
#pragma unroll
                for (int j = 0; j < 8; j++)
                    acc[i][j] = fmaf(a[i], b[j], acc[i][j]);
        }
        __syncthreads();
    }

    float bc[8];
#pragma unroll
    for (int j = 0; j < 8; j++) bc[j] = bias[bn + tx * 8 + j];

#pragma unroll
    for (int i = 0; i < 8; i++) {
        float* Cp = C + (size_t)(bm + ty * 8 + i) * N + bn + tx * 8;
        float4 o0 = make_float4(acc[i][0] + bc[0], acc[i][1] + bc[1],
                                acc[i][2] + bc[2], acc[i][3] + bc[3]);
        float4 o1 = make_float4(acc[i][4] + bc[4], acc[i][5] + bc[5],
                                acc[i][6] + bc[6], acc[i][7] + bc[7]);
        *(float4*)Cp       = o0;
        *(float4*)(Cp + 4) = o1;
    }
}

// ---------------------------------------------------------------------------
// Interleaved RoPE on Q and K. Q additionally scaled by 1/d (the module's
// 1/sqrt(d) times SDPA's 1/sqrt(d)). Double-precision angles so cos/sin match
// the fp32 reference within fp32 rounding.
// ---------------------------------------------------------------------------
__global__ __launch_bounds__(256) void rope_kernel(float* __restrict__ Q,
                                                   float* __restrict__ K)
{
    int idx = blockIdx.x * blockDim.x + threadIdx.x;  // pair index
    const int NPAIR = MTOK * DIMM / 2;
    if (idx >= NPAIR) return;

    int t = idx / (DIMM / 2);          // token 0..4095
    int r = idx % (DIMM / 2);
    int h = r / (HDIM / 2);            // head
    int i = r % (HDIM / 2);            // pair within head
    int pos = t % SEQ;                 // position within sequence

    double invf = pow(10000.0, -2.0 * (double)i / (double)HDIM);
    double ang  = (double)pos * invf;
    double sd, cd;
    sincos(ang, &sd, &cd);
    float c = (float)cd, s = (float)sd;

    int base = t * DIMM + h * HDIM + 2 * i;
    float q0 = Q[base], q1 = Q[base + 1];
    float k0 = K[base], k1 = K[base + 1];
    const float qs = 1.0f / 128.0f;    // 1/d
    Q[base]     = (q0 * c - q1 * s) * qs;
    Q[base + 1] = (q1 * c + q0 * s) * qs;
    K[base]     = k0 * c - k1 * s;
    K[base + 1] = k1 * c + k0 * s;
}

// ---------------------------------------------------------------------------
// Flash attention, fp32. Br=Bc=64, d=128. 256 threads (16x16), each thread:
//   S micro-tile 4x4 (rows=queries, cols=keys), O micro-tile 4x8.
// smem: Qs[d][64] (d-major), Ks[d][64] (d-major), Vs[64][d], Ps[64][64] (j-major)
// ---------------------------------------------------------------------------
#define BR 64
#define BC 64
#define FLASH_SMEM (( (128*64) + (128*64) + (64*128) + (64*64) ) * 4)  // 114688 B

extern __shared__ float fsm[];

__global__ __launch_bounds__(256) void flash_kernel(
    const float* __restrict__ Q, const float* __restrict__ K,
    const float* __restrict__ V, float* __restrict__ O)
{
    float* Qs = fsm;                 // [128][64]
    float* Ks = fsm + 8192;          // [128][64]
    float* Vs = fsm + 16384;         // [64][128]
    float* Ps = fsm + 24576;         // [64][64] (j-major: Ps[j][q])

    const int tid = threadIdx.x;
    const int tx  = tid & 15;        // key/e direction
    const int ty  = tid >> 4;        // query direction
    const int bh  = blockIdx.y;
    const int b   = bh >> 4;
    const int h   = bh & 15;
    const int q0  = blockIdx.x * BR;

    const float* Qg = Q + (size_t)(b * SEQ + q0) * DIMM + h * HDIM;
    const float* Kg = K + (size_t)(b * SEQ) * DIMM + h * HDIM;
    const float* Vg = V + (size_t)(b * SEQ) * DIMM + h * HDIM;

    // Load Q tile transposed (d-major). Conflict-free STS (lane varies q-row).
    for (int i = tid; i < BR * (HDIM / 4); i += 256) {
        int r  = i % BR;
        int c4 = (i / BR) * 4;
        float4 v = *(const float4*)(Qg + (size_t)r * DIMM + c4);
        Qs[(c4 + 0) * BR + r] = v.x;
        Qs[(c4 + 1) * BR + r] = v.y;
        Qs[(c4 + 2) * BR + r] = v.z;
        Qs[(c4 + 3) * BR + r] = v.w;
    }

    float m[4], l[4], acc[4][8];
#pragma unroll
    for (int i = 0; i < 4; i++) {
        m[i] = -INFINITY; l[i] = 0.0f;
#pragma unroll
        for (int e = 0; e < 8; e++) acc[i][e] = 0.0f;
    }

    for (int kt = 0; kt < SEQ / BC; kt++) {
        // Load K tile transposed (d-major)
        const float* Kt = Kg + (size_t)kt * BC * DIMM;
        for (int i = tid; i < BC * (HDIM / 4); i += 256) {
            int r  = i % BC;
            int c4 = (i / BC) * 4;
            float4 v = *(const float4*)(Kt + (size_t)r * DIMM + c4);
            Ks[(c4 + 0) * BC + r] = v.x;
            Ks[(c4 + 1) * BC + r] = v.y;
            Ks[(c4 + 2) * BC + r] = v.z;
            Ks[(c4 + 3) * BC + r] = v.w;
        }
        // Load V tile row-major
        const float* Vt = Vg + (size_t)kt * BC * DIMM;
        for (int i = tid; i < BC * (HDIM / 4); i += 256) {
            int r  = i >> 5;
            int c4 = (i & 31) * 4;
            *(float4*)&Vs[r * HDIM + c4] = *(const float4*)(Vt + (size_t)r * DIMM + c4);
        }
        __syncthreads();

        // S = Q·K^T (q pre-scaled, so these are final logits)
        float s[4][4];
#pragma unroll
        for (int i = 0; i < 4; i++)
#pragma unroll
            for (int j = 0; j < 4; j++) s[i][j] = 0.0f;

        for (int d = 0; d < HDIM; d++) {
            float4 qa = *(const float4*)&Qs[d * BR + ty * 4];
            float4 kb = *(const float4*)&Ks[d * BC + tx * 4];
            float aq[4] = {qa.x, qa.y, qa.z, qa.w};
            float bk[4] = {kb.x, kb.y, kb.z, kb.w};
#pragma unroll
            for (int i = 0; i < 4; i++)
#pragma unroll
                for (int j = 0; j < 4; j++)
                    s[i][j] = fmaf(aq[i], bk[j], s[i][j]);
        }

        // Online softmax per row (16-lane groups share a row set)
#pragma unroll
        for (int i = 0; i < 4; i++) {
            float mt = fmaxf(fmaxf(s[i][0], s[i][1]), fmaxf(s[i][2], s[i][3]));
#pragma unroll
            for (int off = 1; off < 16; off <<= 1)
                mt = fmaxf(mt, __shfl_xor_sync(0xffffffffu, mt, off, 16));
            float mn   = fmaxf(m[i], mt);
            float corr = __expf(m[i] - mn);
            m[i] = mn;
            float ls = 0.0f;
#pragma unroll
            for (int j = 0; j < 4; j++) {
                s[i][j] = __expf(s[i][j] - mn);
                ls += s[i][j];
            }
#pragma unroll
            for (int off = 1; off < 16; off <<= 1)
                ls += __shfl_xor_sync(0xffffffffu, ls, off, 16);
            l[i] = l[i] * corr + ls;
#pragma unroll
            for (int e = 0; e < 8; e++) acc[i][e] *= corr;
        }

        // Stage P (j-major) for the PV GEMM
#pragma unroll
        for (int j = 0; j < 4; j++) {
            *(float4*)&Ps[(tx * 4 + j) * BR + ty * 4] =
                make_float4(s[0][j], s[1][j], s[2][j], s[3][j]);
        }
        __syncthreads();

        // O += P·V
        for (int j = 0; j < BC; j++) {
            float4 pa = *(const float4*)&Ps[j * BR + ty * 4];
            float4 v0 = *(const float4*)&Vs[j * HDIM + tx * 8];
            float4 v1 = *(const float4*)&Vs[j * HDIM + tx * 8 + 4];
            float p[4]  = {pa.x, pa.y, pa.z, pa.w};
            float ve[8] = {v0.x, v0.y, v0.z, v0.w, v1.x, v1.y, v1.z, v1.w};
#pragma unroll
            for (int i = 0; i < 4; i++)
#pragma unroll
                for (int e = 0; e < 8; e++)
                    acc[i][e] = fmaf(p[i], ve[e], acc[i][e]);
        }
        __syncthreads();
    }

    // Epilogue: normalize and store [b, n, h*d]
    float* Og = O + (size_t)(b * SEQ + q0) * DIMM + h * HDIM;
#pragma unroll
    for (int i = 0; i < 4; i++) {
        float inv = 1.0f / l[i];
        float4 o0 = make_float4(acc[i][0] * inv, acc[i][1] * inv,
                                acc[i][2] * inv, acc[i][3] * inv);
        float4 o1 = make_float4(acc[i][4] * inv, acc[i][5] * inv,
                                acc[i][6] * inv, acc[i][7] * inv);
        float* p = Og + (size_t)(ty * 4 + i) * DIMM + tx * 8;
        *(float4*)p       = o0;
        *(float4*)(p + 4) = o1;
    }
}

// ---------------------------------------------------------------------------
extern "C" void kernel_launch(void* const* d_in, const int* in_sizes, int n_in,
                              void* d_out, int out_size)
{
    const float* x  = (const float*)d_in[0];
    const float* Wq = (const float*)d_in[1];
    const float* bq = (const float*)d_in[2];
    const float* Wk = (const float*)d_in[3];
    const float* bk = (const float*)d_in[4];
    const float* Wv = (const float*)d_in[5];
    const float* bv = (const float*)d_in[6];
    const float* Wo = (const float*)d_in[7];
    const float* bo = (const float*)d_in[8];
    float* out = (float*)d_out;

    float *qp, *kp, *vp, *ap;
    cudaGetSymbolAddress((void**)&qp, g_Q);
    cudaGetSymbolAddress((void**)&kp, g_K);
    cudaGetSymbolAddress((void**)&vp, g_V);
    cudaGetSymbolAddress((void**)&ap, g_A);

    cudaFuncSetAttribute(flash_kernel,
                         cudaFuncAttributeMaxDynamicSharedMemorySize, FLASH_SMEM);

    dim3 gg(DIMM / GBN, MTOK / GBM);   // (16, 32)

    sgemm_bias<<<gg, 256>>>(x, Wq, bq, qp, MTOK, DIMM, DIMM);
    sgemm_bias<<<gg, 256>>>(x, Wk, bk, kp, MTOK, DIMM, DIMM);
    sgemm_bias<<<gg, 256>>>(x, Wv, bv, vp, MTOK, DIMM, DIMM);

    int npair = MTOK * DIMM / 2;
    rope_kernel<<<(npair + 255) / 256, 256>>>(qp, kp);

    flash_kernel<<<dim3(SEQ / BR, BATCH * NHEAD), 256, FLASH_SMEM>>>(qp, kp, vp, ap);

    sgemm_bias<<<gg, 256>>>(ap, Wo, bo, out, MTOK, DIMM, DIMM);
}

// round 3
// speedup vs baseline: 1.7936x; 1.7936x over previous
#include <cuda_runtime.h>
#include <cuda_bf16.h>
#include <math.h>
#include <stdint.h>

#define DIMM   2048
#define NHEAD  16
#define HDIM   128
#define SEQ    2048
#define BATCH  2
#define MTOK   (BATCH*SEQ)   // 4096 tokens

// ---------------------------------------------------------------------------
// Device-global scratch (no allocation allowed)
// ---------------------------------------------------------------------------
__device__ float g_Q[(size_t)MTOK * DIMM];
__device__ float g_K[(size_t)MTOK * DIMM];
__device__ float g_V[(size_t)MTOK * DIMM];
__device__ float g_A[(size_t)MTOK * DIMM];

__device__ __nv_bfloat16 g_xh[(size_t)MTOK * DIMM];
__device__ __nv_bfloat16 g_xl[(size_t)MTOK * DIMM];
__device__ __nv_bfloat16 g_Wh[4][(size_t)DIMM * DIMM];
__device__ __nv_bfloat16 g_Wl[4][(size_t)DIMM * DIMM];
__device__ __nv_bfloat16 g_Ah[(size_t)MTOK * DIMM];
__device__ __nv_bfloat16 g_Al[(size_t)MTOK * DIMM];

__device__ float2 g_rt[SEQ * 64];   // RoPE cos/sin table

// ---------------------------------------------------------------------------
// Split fp32 -> bf16 hi + bf16 lo   (x = hi + lo to ~2^-17 relative)
// ---------------------------------------------------------------------------
__global__ __launch_bounds__(256) void split_kernel(
    const float* __restrict__ src, __nv_bfloat16* __restrict__ hi,
    __nv_bfloat16* __restrict__ lo, int n)
{
    int i = (blockIdx.x * blockDim.x + threadIdx.x) * 4;
    if (i >= n) return;
    float4 v = *(const float4*)(src + i);
    float vs[4] = {v.x, v.y, v.z, v.w};
    __nv_bfloat16 h[4], l[4];
#pragma unroll
    for (int j = 0; j < 4; j++) {
        h[j] = __float2bfloat16(vs[j]);
        l[j] = __float2bfloat16(vs[j] - __bfloat162float(h[j]));
    }
    __nv_bfloat162 h0; h0.x = h[0]; h0.y = h[1];
    __nv_bfloat162 h1; h1.x = h[2]; h1.y = h[3];
    __nv_bfloat162 l0; l0.x = l[0]; l0.y = l[1];
    __nv_bfloat162 l1; l1.x = l[2]; l1.y = l[3];
    ((__nv_bfloat162*)(hi + i))[0] = h0;
    ((__nv_bfloat162*)(hi + i))[1] = h1;
    ((__nv_bfloat162*)(lo + i))[0] = l0;
    ((__nv_bfloat162*)(lo + i))[1] = l1;
}

// ---------------------------------------------------------------------------
// bf16x3 tensor-core GEMM: C[M,N] = (Ah+Al)@(Bh+Bl) + bias  (hh+hl+lh terms)
// CTA tile 128x128, BK=32, 256 threads, 8 warps as 2(m) x 4(n), warp 64x32.
// cp.async 2-stage pipeline; ldmatrix x4 (+trans for B); fp32 accum.
// ---------------------------------------------------------------------------
#define AST 40                         // A smem row stride (bf16), pad 8
#define BST 136                        // B smem row stride (bf16), pad 8
#define STG_A_L (128*AST)              // 5120
#define STG_B_H (2*128*AST)            // 10240
#define STG_B_L (STG_B_H + 32*BST)     // 14592
#define STG_SZ  (STG_B_H + 2*32*BST)   // 18944 bf16 elems per stage
#define GEMM_SMEM (2 * STG_SZ * 2)     // 75776 bytes

extern __shared__ __nv_bfloat16 gsm[];

__device__ __forceinline__ uint32_t sm_u32(const void* p) {
    return (uint32_t)__cvta_generic_to_shared(p);
}
__device__ __forceinline__ void cp16(uint32_t dst, const void* src) {
    asm volatile("cp.async.cg.shared.global [%0], [%1], 16;" :: "r"(dst), "l"(src) : "memory");
}
__device__ __forceinline__ void ldsm_x4(uint32_t* r, uint32_t a) {
    asm volatile("ldmatrix.sync.aligned.m8n8.x4.shared.b16 {%0,%1,%2,%3}, [%4];"
                 : "=r"(r[0]), "=r"(r[1]), "=r"(r[2]), "=r"(r[3]) : "r"(a));
}
__device__ __forceinline__ void ldsm_x4t(uint32_t* r, uint32_t a) {
    asm volatile("ldmatrix.sync.aligned.m8n8.x4.trans.shared.b16 {%0,%1,%2,%3}, [%4];"
                 : "=r"(r[0]), "=r"(r[1]), "=r"(r[2]), "=r"(r[3]) : "r"(a));
}
__device__ __forceinline__ void mma_bf16(float* c, const uint32_t* a,
                                         uint32_t b0, uint32_t b1) {
    asm volatile(
        "mma.sync.aligned.m16n8k16.row.col.f32.bf16.bf16.f32 "
        "{%0,%1,%2,%3}, {%4,%5,%6,%7}, {%8,%9}, {%0,%1,%2,%3};"
        : "+f"(c[0]), "+f"(c[1]), "+f"(c[2]), "+f"(c[3])
        : "r"(a[0]), "r"(a[1]), "r"(a[2]), "r"(a[3]), "r"(b0), "r"(b1));
}

__device__ __forceinline__ void gemm_issue_stage(
    __nv_bfloat16* S,
    const __nv_bfloat16* __restrict__ Ah, const __nv_bfloat16* __restrict__ Al,
    const __nv_bfloat16* __restrict__ Bh, const __nv_bfloat16* __restrict__ Bl,
    int bm, int bn, int K, int N, int k0, int tid)
{
#pragma unroll
    for (int r = 0; r < 2; r++) {
        int c = tid + r * 256;
        int m = c >> 2, kc = (c & 3) * 8;
        size_t aoff = (size_t)(bm + m) * K + k0 + kc;
        cp16(sm_u32(S + m * AST + kc), Ah + aoff);
        cp16(sm_u32(S + STG_A_L + m * AST + kc), Al + aoff);
        int k = c >> 4, nc = (c & 15) * 8;
        size_t boff = (size_t)(k0 + k) * N + bn + nc;
        cp16(sm_u32(S + STG_B_H + k * BST + nc), Bh + boff);
        cp16(sm_u32(S + STG_B_L + k * BST + nc), Bl + boff);
    }
}

__global__ __launch_bounds__(256) void gemm_bf3(
    const __nv_bfloat16* __restrict__ Ah, const __nv_bfloat16* __restrict__ Al,
    const __nv_bfloat16* __restrict__ Bh, const __nv_bfloat16* __restrict__ Bl,
    const float* __restrict__ bias, float* __restrict__ C,
    int M, int N, int K)
{
    const int tid  = threadIdx.x;
    const int lane = tid & 31;
    const int wid  = tid >> 5;
    const int wm   = (wid >> 2) * 64;
    const int wn   = (wid & 3) * 32;
    const int bm   = blockIdx.y * 128;
    const int bn   = blockIdx.x * 128;
    const int NT   = K / 32;

    float acc[4][4][4];
#pragma unroll
    for (int mi = 0; mi < 4; mi++)
#pragma unroll
        for (int ni = 0; ni < 4; ni++)
#pragma unroll
            for (int e = 0; e < 4; e++) acc[mi][ni][e] = 0.0f;

    gemm_issue_stage(gsm, Ah, Al, Bh, Bl, bm, bn, K, N, 0, tid);
    asm volatile("cp.async.commit_group;" ::: "memory");

    for (int kt = 0; kt < NT; kt++) {
        if (kt + 1 < NT) {
            gemm_issue_stage(gsm + ((kt + 1) & 1) * STG_SZ,
                             Ah, Al, Bh, Bl, bm, bn, K, N, (kt + 1) * 32, tid);
            asm volatile("cp.async.commit_group;" ::: "memory");
            asm volatile("cp.async.wait_group 1;" ::: "memory");
        } else {
            asm volatile("cp.async.wait_group 0;" ::: "memory");
        }
        __syncthreads();

        const __nv_bfloat16* S = gsm + (kt & 1) * STG_SZ;
#pragma unroll
        for (int ks = 0; ks < 2; ks++) {
            uint32_t ah[4][4], al[4][4], bh[2][4], bl[2][4];
            const int arow = lane & 15;
            const int acol = ks * 16 + (lane >> 4) * 8;
#pragma unroll
            for (int mi = 0; mi < 4; mi++) {
                const __nv_bfloat16* pa = S + (wm + mi * 16 + arow) * AST + acol;
                ldsm_x4(ah[mi], sm_u32(pa));
                ldsm_x4(al[mi], sm_u32(pa + STG_A_L));
            }
            const int brow = ks * 16 + (lane & 15);
#pragma unroll
            for (int np = 0; np < 2; np++) {
                const __nv_bfloat16* pb =
                    S + STG_B_H + brow * BST + wn + np * 16 + (lane >> 4) * 8;
                ldsm_x4t(bh[np], sm_u32(pb));
                ldsm_x4t(bl[np], sm_u32(pb + (STG_B_L - STG_B_H)));
            }
            // hi*hi
#pragma unroll
            for (int mi = 0; mi < 4; mi++)
#pragma unroll
                for (int ni = 0; ni < 4; ni++)
                    mma_bf16(acc[mi][ni], ah[mi],
                             bh[ni >> 1][(ni & 1) * 2], bh[ni >> 1][(ni & 1) * 2 + 1]);
            // hi*lo
#pragma unroll
            for (int mi = 0; mi < 4; mi++)
#pragma unroll
                for (int ni = 0; ni < 4; ni++)
                    mma_bf16(acc[mi][ni], ah[mi],
                             bl[ni >> 1][(ni & 1) * 2], bl[ni >> 1][(ni & 1) * 2 + 1]);
            // lo*hi
#pragma unroll
            for (int mi = 0; mi < 4; mi++)
#pragma unroll
                for (int ni = 0; ni < 4; ni++)
                    mma_bf16(acc[mi][ni], al[mi],
                             bh[ni >> 1][(ni & 1) * 2], bh[ni >> 1][(ni & 1) * 2 + 1]);
        }
        __syncthreads();
    }

    // Epilogue: add bias, store fp32
#pragma unroll
    for (int mi = 0; mi < 4; mi++) {
#pragma unroll
        for (int ni = 0; ni < 4; ni++) {
            int row = bm + wm + mi * 16 + (lane >> 2);
            int col = bn + wn + ni * 8 + (lane & 3) * 2;
            float2 bb = *(const float2*)(bias + col);
            float2 o0 = make_float2(acc[mi][ni][0] + bb.x, acc[mi][ni][1] + bb.y);
            float2 o1 = make_float2(acc[mi][ni][2] + bb.x, acc[mi][ni][3] + bb.y);
            *(float2*)(C + (size_t)row * N + col)       = o0;
            *(float2*)(C + (size_t)(row + 8) * N + col) = o1;
        }
    }
}

// ---------------------------------------------------------------------------
// RoPE: table build (double precision, tiny) + memory-bound apply
// ---------------------------------------------------------------------------
__global__ __launch_bounds__(256) void rope_table_kernel()
{
    int idx = blockIdx.x * blockDim.x + threadIdx.x;
    if (idx >= SEQ * 64) return;
    int pos = idx >> 6, i = idx & 63;
    double invf = pow(10000.0, -(double)i / 64.0);
    double sd, cd;
    sincos((double)pos * invf, &sd, &cd);
    g_rt[idx] = make_float2((float)cd, (float)sd);
}

__global__ __launch_bounds__(256) void rope_apply_kernel(float* __restrict__ Q,
                                                         float* __restrict__ K)
{
    int idx = blockIdx.x * blockDim.x + threadIdx.x;  // pair index
    const int NPAIR = MTOK * DIMM / 2;
    if (idx >= NPAIR) return;

    int t = idx / (DIMM / 2);
    int r = idx % (DIMM / 2);
    int h = r / (HDIM / 2);
    int i = r % (HDIM / 2);

    float2 cs = g_rt[(t & (SEQ - 1)) * 64 + i];
    float c = cs.x, s = cs.y;

    int base = t * DIMM + h * HDIM + 2 * i;
    float q0 = Q[base], q1 = Q[base + 1];
    float k0 = K[base], k1 = K[base + 1];
    const float qs = 1.0f / 128.0f;    // 1/d (module scale * SDPA scale)
    Q[base]     = (q0 * c - q1 * s) * qs;
    Q[base + 1] = (q1 * c + q0 * s) * qs;
    K[base]     = k0 * c - k1 * s;
    K[base + 1] = k1 * c + k0 * s;
}

// ---------------------------------------------------------------------------
// Flash attention, fp32 (unchanged from R2 passing kernel)
// ---------------------------------------------------------------------------
#define BR 64
#define BC 64
#define FLASH_SMEM (( (128*64) + (128*64) + (64*128) + (64*64) ) * 4)  // 114688 B

extern __shared__ float fsm[];

__global__ __launch_bounds__(256) void flash_kernel(
    const float* __restrict__ Q, const float* __restrict__ K,
    const float* __restrict__ V, float* __restrict__ O)
{
    float* Qs = fsm;                 // [128][64]
    float* Ks = fsm + 8192;          // [128][64]
    float* Vs = fsm + 16384;         // [64][128]
    float* Ps = fsm + 24576;         // [64][64] (j-major)

    const int tid = threadIdx.x;
    const int tx  = tid & 15;
    const int ty  = tid >> 4;
    const int bh  = blockIdx.y;
    const int b   = bh >> 4;
    const int h   = bh & 15;
    const int q0  = blockIdx.x * BR;

    const float* Qg = Q + (size_t)(b * SEQ + q0) * DIMM + h * HDIM;
    const float* Kg = K + (size_t)(b * SEQ) * DIMM + h * HDIM;
    const float* Vg = V + (size_t)(b * SEQ) * DIMM + h * HDIM;

    for (int i = tid; i < BR * (HDIM / 4); i += 256) {
        int r  = i % BR;
        int c4 = (i / BR) * 4;
        float4 v = *(const float4*)(Qg + (size_t)r * DIMM + c4);
        Qs[(c4 + 0) * BR + r] = v.x;
        Qs[(c4 + 1) * BR + r] = v.y;
        Qs[(c4 + 2) * BR + r] = v.z;
        Qs[(c4 + 3) * BR + r] = v.w;
    }

    float m[4], l[4], acc[4][8];
#pragma unroll
    for (int i = 0; i < 4; i++) {
        m[i] = -INFINITY; l[i] = 0.0f;
#pragma unroll
        for (int e = 0; e < 8; e++) acc[i][e] = 0.0f;
    }

    for (int kt = 0; kt < SEQ / BC; kt++) {
        const float* Kt = Kg + (size_t)kt * BC * DIMM;
        for (int i = tid; i < BC * (HDIM / 4); i += 256) {
            int r  = i % BC;
            int c4 = (i / BC) * 4;
            float4 v = *(const float4*)(Kt + (size_t)r * DIMM + c4);
            Ks[(c4 + 0) * BC + r] = v.x;
            Ks[(c4 + 1) * BC + r] = v.y;
            Ks[(c4 + 2) * BC + r] = v.z;
            Ks[(c4 + 3) * BC + r] = v.w;
        }
        const float* Vt = Vg + (size_t)kt * BC * DIMM;
        for (int i = tid; i < BC * (HDIM / 4); i += 256) {
            int r  = i >> 5;
            int c4 = (i & 31) * 4;
            *(float4*)&Vs[r * HDIM + c4] = *(const float4*)(Vt + (size_t)r * DIMM + c4);
        }
        __syncthreads();

        float s[4][4];
#pragma unroll
        for (int i = 0; i < 4; i++)
#pragma unroll
            for (int j = 0; j < 4; j++) s[i][j] = 0.0f;

        for (int d = 0; d < HDIM; d++) {
            float4 qa = *(const float4*)&Qs[d * BR + ty * 4];
            float4 kb = *(const float4*)&Ks[d * BC + tx * 4];
            float aq[4] = {qa.x, qa.y, qa.z, qa.w};
            float bk[4] = {kb.x, kb.y, kb.z, kb.w};
#pragma unroll
            for (int i = 0; i < 4; i++)
#pragma unroll
                for (int j = 0; j < 4; j++)
                    s[i][j] = fmaf(aq[i], bk[j], s[i][j]);
        }

#pragma unroll
        for (int i = 0; i < 4; i++) {
            float mt = fmaxf(fmaxf(s[i][0], s[i][1]), fmaxf(s[i][2], s[i][3]));
#pragma unroll
            for (int off = 1; off < 16; off <<= 1)
                mt = fmaxf(mt, __shfl_xor_sync(0xffffffffu, mt, off, 16));
            float mn   = fmaxf(m[i], mt);
            float corr = __expf(m[i] - mn);
            m[i] = mn;
            float ls = 0.0f;
#pragma unroll
            for (int j = 0; j < 4; j++) {
                s[i][j] = __expf(s[i][j] - mn);
                ls += s[i][j];
            }
#pragma unroll
            for (int off = 1; off < 16; off <<= 1)
                ls += __shfl_xor_sync(0xffffffffu, ls, off, 16);
            l[i] = l[i] * corr + ls;
#pragma unroll
            for (int e = 0; e < 8; e++) acc[i][e] *= corr;
        }

#pragma unroll
        for (int j = 0; j < 4; j++) {
            *(float4*)&Ps[(tx * 4 + j) * BR + ty * 4] =
                make_float4(s[0][j], s[1][j], s[2][j], s[3][j]);
        }
        __syncthreads();

        for (int j = 0; j < BC; j++) {
            float4 pa = *(const float4*)&Ps[j * BR + ty * 4];
            float4 v0 = *(const float4*)&Vs[j * HDIM + tx * 8];
            float4 v1 = *(const float4*)&Vs[j * HDIM + tx * 8 + 4];
            float p[4]  = {pa.x, pa.y, pa.z, pa.w};
            float ve[8] = {v0.x, v0.y, v0.z, v0.w, v1.x, v1.y, v1.z, v1.w};
#pragma unroll
            for (int i = 0; i < 4; i++)
#pragma unroll
                for (int e = 0; e < 8; e++)
                    acc[i][e] = fmaf(p[i], ve[e], acc[i][e]);
        }
        __syncthreads();
    }

    float* Og = O + (size_t)(b * SEQ + q0) * DIMM + h * HDIM;
#pragma unroll
    for (int i = 0; i < 4; i++) {
        float inv = 1.0f / l[i];
        float4 o0 = make_float4(acc[i][0] * inv, acc[i][1] * inv,
                                acc[i][2] * inv, acc[i][3] * inv);
        float4 o1 = make_float4(acc[i][4] * inv, acc[i][5] * inv,
                                acc[i][6] * inv, acc[i][7] * inv);
        float* p = Og + (size_t)(ty * 4 + i) * DIMM + tx * 8;
        *(float4*)p       = o0;
        *(float4*)(p + 4) = o1;
    }
}

// ---------------------------------------------------------------------------
extern "C" void kernel_launch(void* const* d_in, const int* in_sizes, int n_in,
                              void* d_out, int out_size)
{
    const float* x  = (const float*)d_in[0];
    const float* Wq = (const float*)d_in[1];
    const float* bq = (const float*)d_in[2];
    const float* Wk = (const float*)d_in[3];
    const float* bk = (const float*)d_in[4];
    const float* Wv = (const float*)d_in[5];
    const float* bv = (const float*)d_in[6];
    const float* Wo = (const float*)d_in[7];
    const float* bo = (const float*)d_in[8];
    float* out = (float*)d_out;

    float *qp, *kp, *vp, *ap;
    __nv_bfloat16 *xh, *xl, *wh, *wl, *ah, *al;
    cudaGetSymbolAddress((void**)&qp, g_Q);
    cudaGetSymbolAddress((void**)&kp, g_K);
    cudaGetSymbolAddress((void**)&vp, g_V);
    cudaGetSymbolAddress((void**)&ap, g_A);
    cudaGetSymbolAddress((void**)&xh, g_xh);
    cudaGetSymbolAddress((void**)&xl, g_xl);
    cudaGetSymbolAddress((void**)&wh, g_Wh);
    cudaGetSymbolAddress((void**)&wl, g_Wl);
    cudaGetSymbolAddress((void**)&ah, g_Ah);
    cudaGetSymbolAddress((void**)&al, g_Al);

    cudaFuncSetAttribute(flash_kernel,
                         cudaFuncAttributeMaxDynamicSharedMemorySize, FLASH_SMEM);
    cudaFuncSetAttribute(gemm_bf3,
                         cudaFuncAttributeMaxDynamicSharedMemorySize, GEMM_SMEM);

    const size_t WSZ = (size_t)DIMM * DIMM;
    const int NX = MTOK * DIMM;          // 8388608
    const int NW = DIMM * DIMM;          // 4194304

    // Split inputs/weights to bf16 hi/lo
    split_kernel<<<NX / 4 / 256, 256>>>(x,  xh, xl, NX);
    split_kernel<<<NW / 4 / 256, 256>>>(Wq, wh + 0 * WSZ, wl + 0 * WSZ, NW);
    split_kernel<<<NW / 4 / 256, 256>>>(Wk, wh + 1 * WSZ, wl + 1 * WSZ, NW);
    split_kernel<<<NW / 4 / 256, 256>>>(Wv, wh + 2 * WSZ, wl + 2 * WSZ, NW);
    split_kernel<<<NW / 4 / 256, 256>>>(Wo, wh + 3 * WSZ, wl + 3 * WSZ, NW);

    dim3 gg(DIMM / 128, MTOK / 128);     // (16, 32)

    gemm_bf3<<<gg, 256, GEMM_SMEM>>>(xh, xl, wh + 0 * WSZ, wl + 0 * WSZ, bq, qp,
                                     MTOK, DIMM, DIMM);
    gemm_bf3<<<gg, 256, GEMM_SMEM>>>(xh, xl, wh + 1 * WSZ, wl + 1 * WSZ, bk, kp,
                                     MTOK, DIMM, DIMM);
    gemm_bf3<<<gg, 256, GEMM_SMEM>>>(xh, xl, wh + 2 * WSZ, wl + 2 * WSZ, bv, vp,
                                     MTOK, DIMM, DIMM);

    rope_table_kernel<<<(SEQ * 64) / 256, 256>>>();
    int npair = MTOK * DIMM / 2;
    rope_apply_kernel<<<(npair + 255) / 256, 256>>>(qp, kp);

    flash_kernel<<<dim3(SEQ / BR, BATCH * NHEAD), 256, FLASH_SMEM>>>(qp, kp, vp, ap);

    split_kernel<<<NX / 4 / 256, 256>>>(ap, ah, al, NX);
    gemm_bf3<<<gg, 256, GEMM_SMEM>>>(ah, al, wh + 3 * WSZ, wl + 3 * WSZ, bo, out,
                                     MTOK, DIMM, DIMM);
}

// round 7
// speedup vs baseline: 3.5881x; 2.0005x over previous
#include <cuda_runtime.h>
#include <cuda_bf16.h>
#include <math.h>
#include <stdint.h>

#define DIMM   2048
#define NHEAD  16
#define HDIM   128
#define SEQ    2048
#define BATCH  2
#define MTOK   (BATCH*SEQ)   // 4096 tokens

// ---------------------------------------------------------------------------
// Device-global scratch (no allocation allowed)
// ---------------------------------------------------------------------------
__device__ float g_Q[(size_t)MTOK * DIMM];
__device__ float g_K[(size_t)MTOK * DIMM];

__device__ __nv_bfloat16 g_xh[(size_t)MTOK * DIMM];
__device__ __nv_bfloat16 g_xl[(size_t)MTOK * DIMM];
__device__ __nv_bfloat16 g_Wh[4][(size_t)DIMM * DIMM];
__device__ __nv_bfloat16 g_Wl[4][(size_t)DIMM * DIMM];
__device__ __nv_bfloat16 g_Qh[(size_t)MTOK * DIMM];
__device__ __nv_bfloat16 g_Ql[(size_t)MTOK * DIMM];
__device__ __nv_bfloat16 g_Kh[(size_t)MTOK * DIMM];
__device__ __nv_bfloat16 g_Kl[(size_t)MTOK * DIMM];
__device__ __nv_bfloat16 g_Vh[(size_t)MTOK * DIMM];
__device__ __nv_bfloat16 g_Vl[(size_t)MTOK * DIMM];
__device__ __nv_bfloat16 g_Ah[(size_t)MTOK * DIMM];
__device__ __nv_bfloat16 g_Al[(size_t)MTOK * DIMM];

__device__ float2 g_rt[SEQ * 64];   // RoPE cos/sin table

// ---------------------------------------------------------------------------
// Common PTX helpers
// ---------------------------------------------------------------------------
__device__ __forceinline__ uint32_t sm_u32(const void* p) {
    return (uint32_t)__cvta_generic_to_shared(p);
}
__device__ __forceinline__ void cp16(uint32_t dst, const void* src) {
    asm volatile("cp.async.cg.shared.global [%0], [%1], 16;" :: "r"(dst), "l"(src) : "memory");
}
__device__ __forceinline__ void ldsm_x4(uint32_t* r, uint32_t a) {
    asm volatile("ldmatrix.sync.aligned.m8n8.x4.shared.b16 {%0,%1,%2,%3}, [%4];"
                 : "=r"(r[0]), "=r"(r[1]), "=r"(r[2]), "=r"(r[3]) : "r"(a));
}
__device__ __forceinline__ void ldsm_x4t(uint32_t* r, uint32_t a) {
    asm volatile("ldmatrix.sync.aligned.m8n8.x4.trans.shared.b16 {%0,%1,%2,%3}, [%4];"
                 : "=r"(r[0]), "=r"(r[1]), "=r"(r[2]), "=r"(r[3]) : "r"(a));
}
__device__ __forceinline__ void mma_bf16(float* c, const uint32_t* a,
                                         uint32_t b0, uint32_t b1) {
    asm volatile(
        "mma.sync.aligned.m16n8k16.row.col.f32.bf16.bf16.f32 "
        "{%0,%1,%2,%3}, {%4,%5,%6,%7}, {%8,%9}, {%0,%1,%2,%3};"
        : "+f"(c[0]), "+f"(c[1]), "+f"(c[2]), "+f"(c[3])
        : "r"(a[0]), "r"(a[1]), "r"(a[2]), "r"(a[3]), "r"(b0), "r"(b1));
}
// pack2(lo, hi): bf16x2 with lo in lower half
__device__ __forceinline__ uint32_t pack2(float lo, float hi) {
    uint32_t r;
    asm("cvt.rn.bf16x2.f32 %0, %1, %2;" : "=r"(r) : "f"(hi), "f"(lo));
    return r;
}
__device__ __forceinline__ float fexp2(float x) {
    float y;
    asm("ex2.approx.ftz.f32 %0, %1;" : "=f"(y) : "f"(x));
    return y;
}

// ---------------------------------------------------------------------------
// Split fp32 -> bf16 hi + bf16 lo
// ---------------------------------------------------------------------------
__global__ __launch_bounds__(256) void split_kernel(
    const float* __restrict__ src, __nv_bfloat16* __restrict__ hi,
    __nv_bfloat16* __restrict__ lo, int n)
{
    int i = (blockIdx.x * blockDim.x + threadIdx.x) * 4;
    if (i >= n) return;
    float4 v = *(const float4*)(src + i);
    float vs[4] = {v.x, v.y, v.z, v.w};
    __nv_bfloat16 h[4], l[4];
#pragma unroll
    for (int j = 0; j < 4; j++) {
        h[j] = __float2bfloat16(vs[j]);
        l[j] = __float2bfloat16(vs[j] - __bfloat162float(h[j]));
    }
    __nv_bfloat162 h0; h0.x = h[0]; h0.y = h[1];
    __nv_bfloat162 h1; h1.x = h[2]; h1.y = h[3];
    __nv_bfloat162 l0; l0.x = l[0]; l0.y = l[1];
    __nv_bfloat162 l1; l1.x = l[2]; l1.y = l[3];
    ((__nv_bfloat162*)(hi + i))[0] = h0;
    ((__nv_bfloat162*)(hi + i))[1] = h1;
    ((__nv_bfloat162*)(lo + i))[0] = l0;
    ((__nv_bfloat162*)(lo + i))[1] = l1;
}

// ---------------------------------------------------------------------------
// bf16x3 tensor-core GEMM: C = (Ah+Al)@(Bh+Bl) + bias  (hh+hl+lh)
// If Ch != nullptr, epilogue writes bf16 hi/lo split to (Ch, Cl) instead of
// fp32 C (used for the V projection to feed flash directly).
// ---------------------------------------------------------------------------
#define AST 40
#define BST 136
#define STG_A_L (128*AST)
#define STG_B_H (2*128*AST)
#define STG_B_L (STG_B_H + 32*BST)
#define STG_SZ  (STG_B_H + 2*32*BST)
#define GEMM_SMEM (2 * STG_SZ * 2)

extern __shared__ __nv_bfloat16 gsm[];

__device__ __forceinline__ void gemm_issue_stage(
    __nv_bfloat16* S,
    const __nv_bfloat16* __restrict__ Ah, const __nv_bfloat16* __restrict__ Al,
    const __nv_bfloat16* __restrict__ Bh, const __nv_bfloat16* __restrict__ Bl,
    int bm, int bn, int K, int N, int k0, int tid)
{
#pragma unroll
    for (int r = 0; r < 2; r++) {
        int c = tid + r * 256;
        int m = c >> 2, kc = (c & 3) * 8;
        size_t aoff = (size_t)(bm + m) * K + k0 + kc;
        cp16(sm_u32(S + m * AST + kc), Ah + aoff);
        cp16(sm_u32(S + STG_A_L + m * AST + kc), Al + aoff);
        int k = c >> 4, nc = (c & 15) * 8;
        size_t boff = (size_t)(k0 + k) * N + bn + nc;
        cp16(sm_u32(S + STG_B_H + k * BST + nc), Bh + boff);
        cp16(sm_u32(S + STG_B_L + k * BST + nc), Bl + boff);
    }
}

__global__ __launch_bounds__(256) void gemm_bf3(
    const __nv_bfloat16* __restrict__ Ah, const __nv_bfloat16* __restrict__ Al,
    const __nv_bfloat16* __restrict__ Bh, const __nv_bfloat16* __restrict__ Bl,
    const float* __restrict__ bias, float* __restrict__ C,
    __nv_bfloat16* __restrict__ Ch, __nv_bfloat16* __restrict__ Cl,
    int M, int N, int K)
{
    const int tid  = threadIdx.x;
    const int lane = tid & 31;
    const int wid  = tid >> 5;
    const int wm   = (wid >> 2) * 64;
    const int wn   = (wid & 3) * 32;
    const int bm   = blockIdx.y * 128;
    const int bn   = blockIdx.x * 128;
    const int NT   = K / 32;

    float acc[4][4][4];
#pragma unroll
    for (int mi = 0; mi < 4; mi++)
#pragma unroll
        for (int ni = 0; ni < 4; ni++)
#pragma unroll
            for (int e = 0; e < 4; e++) acc[mi][ni][e] = 0.0f;

    gemm_issue_stage(gsm, Ah, Al, Bh, Bl, bm, bn, K, N, 0, tid);
    asm volatile("cp.async.commit_group;" ::: "memory");

    for (int kt = 0; kt < NT; kt++) {
        if (kt + 1 < NT) {
            gemm_issue_stage(gsm + ((kt + 1) & 1) * STG_SZ,
                             Ah, Al, Bh, Bl, bm, bn, K, N, (kt + 1) * 32, tid);
            asm volatile("cp.async.commit_group;" ::: "memory");
            asm volatile("cp.async.wait_group 1;" ::: "memory");
        } else {
            asm volatile("cp.async.wait_group 0;" ::: "memory");
        }
        __syncthreads();

        const __nv_bfloat16* S = gsm + (kt & 1) * STG_SZ;
#pragma unroll
        for (int ks = 0; ks < 2; ks++) {
            uint32_t ah[4][4], al[4][4], bh[2][4], bl[2][4];
            const int arow = lane & 15;
            const int acol = ks * 16 + (lane >> 4) * 8;
#pragma unroll
            for (int mi = 0; mi < 4; mi++) {
                const __nv_bfloat16* pa = S + (wm + mi * 16 + arow) * AST + acol;
                ldsm_x4(ah[mi], sm_u32(pa));
                ldsm_x4(al[mi], sm_u32(pa + STG_A_L));
            }
            const int brow = ks * 16 + (lane & 15);
#pragma unroll
            for (int np = 0; np < 2; np++) {
                const __nv_bfloat16* pb =
                    S + STG_B_H + brow * BST + wn + np * 16 + (lane >> 4) * 8;
                ldsm_x4t(bh[np], sm_u32(pb));
                ldsm_x4t(bl[np], sm_u32(pb + (STG_B_L - STG_B_H)));
            }
#pragma unroll
            for (int mi = 0; mi < 4; mi++)
#pragma unroll
                for (int ni = 0; ni < 4; ni++)
                    mma_bf16(acc[mi][ni], ah[mi],
                             bh[ni >> 1][(ni & 1) * 2], bh[ni >> 1][(ni & 1) * 2 + 1]);
#pragma unroll
            for (int mi = 0; mi < 4; mi++)
#pragma unroll
                for (int ni = 0; ni < 4; ni++)
                    mma_bf16(acc[mi][ni], ah[mi],
                             bl[ni >> 1][(ni & 1) * 2], bl[ni >> 1][(ni & 1) * 2 + 1]);
#pragma unroll
            for (int mi = 0; mi < 4; mi++)
#pragma unroll
                for (int ni = 0; ni < 4; ni++)
                    mma_bf16(acc[mi][ni], al[mi],
                             bh[ni >> 1][(ni & 1) * 2], bh[ni >> 1][(ni & 1) * 2 + 1]);
        }
        __syncthreads();
    }

#pragma unroll
    for (int mi = 0; mi < 4; mi++) {
#pragma unroll
        for (int ni = 0; ni < 4; ni++) {
            int row = bm + wm + mi * 16 + (lane >> 2);
            int col = bn + wn + ni * 8 + (lane & 3) * 2;
            float2 bb = *(const float2*)(bias + col);
            float f0 = acc[mi][ni][0] + bb.x, f1 = acc[mi][ni][1] + bb.y;
            float f2 = acc[mi][ni][2] + bb.x, f3 = acc[mi][ni][3] + bb.y;
            if (Ch) {
                uint32_t h0 = pack2(f0, f1);
                uint32_t l0 = pack2(f0 - __int_as_float(h0 << 16),
                                    f1 - __int_as_float(h0 & 0xffff0000u));
                uint32_t h1 = pack2(f2, f3);
                uint32_t l1 = pack2(f2 - __int_as_float(h1 << 16),
                                    f3 - __int_as_float(h1 & 0xffff0000u));
                *(uint32_t*)(Ch + (size_t)row * N + col)       = h0;
                *(uint32_t*)(Cl + (size_t)row * N + col)       = l0;
                *(uint32_t*)(Ch + (size_t)(row + 8) * N + col) = h1;
                *(uint32_t*)(Cl + (size_t)(row + 8) * N + col) = l1;
            } else {
                *(float2*)(C + (size_t)row * N + col)       = make_float2(f0, f1);
                *(float2*)(C + (size_t)(row + 8) * N + col) = make_float2(f2, f3);
            }
        }
    }
}

// ---------------------------------------------------------------------------
// RoPE table (double precision)
// ---------------------------------------------------------------------------
__global__ __launch_bounds__(256) void rope_table_kernel()
{
    int idx = blockIdx.x * blockDim.x + threadIdx.x;
    if (idx >= SEQ * 64) return;
    int pos = idx >> 6, i = idx & 63;
    double invf = pow(10000.0, -(double)i / 64.0);
    double sd, cd;
    sincos((double)pos * invf, &sd, &cd);
    g_rt[idx] = make_float2((float)cd, (float)sd);
}

// ---------------------------------------------------------------------------
// Fused RoPE + scale + bf16 hi/lo split for Q and K.
// Q scaled by log2(e)/128 so flash logits are in the exp2 domain.
// ---------------------------------------------------------------------------
__global__ __launch_bounds__(256) void rope_split_kernel(
    const float* __restrict__ Q, const float* __restrict__ K)
{
    int idx = blockIdx.x * blockDim.x + threadIdx.x;  // pair index
    const int NPAIR = MTOK * DIMM / 2;
    if (idx >= NPAIR) return;

    int t = idx / (DIMM / 2);
    int r = idx % (DIMM / 2);
    int h = r / (HDIM / 2);
    int i = r % (HDIM / 2);

    float2 cs = g_rt[(t & (SEQ - 1)) * 64 + i];
    float c = cs.x, s = cs.y;

    int base = t * DIMM + h * HDIM + 2 * i;
    float q0 = Q[base], q1 = Q[base + 1];
    float k0 = K[base], k1 = K[base + 1];
    const float qs = 1.4426950408889634f / 128.0f;  // log2(e)/d

    float x0 = (q0 * c - q1 * s) * qs;
    float x1 = (q1 * c + q0 * s) * qs;
    float y0 = k0 * c - k1 * s;
    float y1 = k1 * c + k0 * s;

    uint32_t xh = pack2(x0, x1);
    float xr0 = x0 - __int_as_float(xh << 16);
    float xr1 = x1 - __int_as_float(xh & 0xffff0000u);
    uint32_t xl = pack2(xr0, xr1);
    uint32_t yh = pack2(y0, y1);
    float yr0 = y0 - __int_as_float(yh << 16);
    float yr1 = y1 - __int_as_float(yh & 0xffff0000u);
    uint32_t yl = pack2(yr0, yr1);

    *(uint32_t*)&g_Qh[base] = xh;
    *(uint32_t*)&g_Ql[base] = xl;
    *(uint32_t*)&g_Kh[base] = yh;
    *(uint32_t*)&g_Kl[base] = yl;
}

// ---------------------------------------------------------------------------
// Tensor-core flash attention (bf16x3 for S=QK^T and O=PV).
// BR=128 (8 warps x 16 rows), BC=64, d=128. 256 threads.
// smem: Qh[0:32K) Ql[32K:64K) + 2 stages of {Kh,Kl,Vh,Vl} 16K each = 192KB.
// XOR-swizzled 256B rows. Epilogue writes bf16 hi/lo of O directly.
// ---------------------------------------------------------------------------
#define FQH 0u
#define FQL 32768u
#define FST(s) (65536u + (uint32_t)(s) * 65536u)
#define FLASH_SMEM 196608

__device__ __forceinline__ uint32_t fswz(uint32_t row, uint32_t colbyte) {
    uint32_t off = row * 256u + colbyte;
    return off ^ ((row & 7u) << 4);
}

__device__ __forceinline__ void flash_load_kv(
    uint32_t sb, int stage, size_t kb,
    const __nv_bfloat16* __restrict__ Kh_, const __nv_bfloat16* __restrict__ Kl_,
    const __nv_bfloat16* __restrict__ Vh_, const __nv_bfloat16* __restrict__ Vl_,
    int tid)
{
    uint32_t base = sb + FST(stage);
#pragma unroll
    for (int c = tid; c < 1024; c += 256) {
        uint32_t row = c >> 4, ch = c & 15;
        uint32_t d = fswz(row, ch * 16);
        size_t so = kb + (size_t)row * DIMM + ch * 8;
        cp16(base + d,          Kh_ + so);
        cp16(base + 16384u + d, Kl_ + so);
        cp16(base + 32768u + d, Vh_ + so);
        cp16(base + 49152u + d, Vl_ + so);
    }
}

__global__ __launch_bounds__(256) void flash_tc(
    const __nv_bfloat16* __restrict__ Qh_, const __nv_bfloat16* __restrict__ Ql_,
    const __nv_bfloat16* __restrict__ Kh_, const __nv_bfloat16* __restrict__ Kl_,
    const __nv_bfloat16* __restrict__ Vh_, const __nv_bfloat16* __restrict__ Vl_,
    __nv_bfloat16* __restrict__ Ah, __nv_bfloat16* __restrict__ Al)
{
    const uint32_t sb = sm_u32(gsm);
    const int tid  = threadIdx.x;
    const int lane = tid & 31;
    const int wid  = tid >> 5;
    const int wr   = wid * 16;
    const int bh   = blockIdx.y;
    const int b    = bh >> 4;
    const int h    = bh & 15;
    const int q0   = blockIdx.x * 128;

    const size_t qg = (size_t)(b * SEQ + q0) * DIMM + h * HDIM;
    const size_t kg0 = (size_t)(b * SEQ) * DIMM + h * HDIM;

    // Q tile load (hi+lo), swizzled
#pragma unroll
    for (int c = tid; c < 2048; c += 256) {
        uint32_t row = c >> 4, ch = c & 15;
        uint32_t d = fswz(row, ch * 16);
        size_t so = qg + (size_t)row * DIMM + ch * 8;
        cp16(sb + FQH + d, Qh_ + so);
        cp16(sb + FQL + d, Ql_ + so);
    }
    flash_load_kv(sb, 0, kg0, Kh_, Kl_, Vh_, Vl_, tid);
    asm volatile("cp.async.commit_group;" ::: "memory");

    float acc_o[16][4];
#pragma unroll
    for (int ni = 0; ni < 16; ni++)
#pragma unroll
        for (int e = 0; e < 4; e++) acc_o[ni][e] = 0.0f;
    float m_a = -INFINITY, m_b = -INFINITY, l_a = 0.0f, l_b = 0.0f;

    const uint32_t arow = (uint32_t)(wr + (lane & 15));
    const uint32_t chalf = (uint32_t)((lane >> 4) * 16);

    for (int kt = 0; kt < SEQ / 64; kt++) {
        asm volatile("cp.async.wait_group 0;" ::: "memory");
        __syncthreads();
        if (kt + 1 < SEQ / 64) {
            flash_load_kv(sb, (kt + 1) & 1, kg0 + (size_t)(kt + 1) * 64 * DIMM,
                          Kh_, Kl_, Vh_, Vl_, tid);
            asm volatile("cp.async.commit_group;" ::: "memory");
        }
        const uint32_t kbase = sb + FST(kt & 1);

        // ---- S = Q K^T (bf16x3) ----
        float s[8][4];
#pragma unroll
        for (int j = 0; j < 8; j++)
#pragma unroll
            for (int e = 0; e < 4; e++) s[j][e] = 0.0f;

#pragma unroll
        for (int kc = 0; kc < 8; kc++) {
            uint32_t cb = (uint32_t)kc * 32 + chalf;
            uint32_t aq[4], aql[4];
            ldsm_x4(aq,  sb + FQH + fswz(arow, cb));
            ldsm_x4(aql, sb + FQL + fswz(arow, cb));
#pragma unroll
            for (int g = 0; g < 4; g++) {
                uint32_t krow = (uint32_t)(g * 16 + (lane & 15));
                uint32_t kh4[4], kl4[4];
                ldsm_x4(kh4, kbase + fswz(krow, cb));
                ldsm_x4(kl4, kbase + 16384u + fswz(krow, cb));
                mma_bf16(s[2 * g],     aq,  kh4[0], kh4[2]);
                mma_bf16(s[2 * g],     aq,  kl4[0], kl4[2]);
                mma_bf16(s[2 * g],     aql, kh4[0], kh4[2]);
                mma_bf16(s[2 * g + 1], aq,  kh4[1], kh4[3]);
                mma_bf16(s[2 * g + 1], aq,  kl4[1], kl4[3]);
                mma_bf16(s[2 * g + 1], aql, kh4[1], kh4[3]);
            }
        }

        // ---- online softmax (rows: a = lane>>2, b = +8) ----
        float mxa = -INFINITY, mxb = -INFINITY;
#pragma unroll
        for (int j = 0; j < 8; j++) {
            mxa = fmaxf(mxa, fmaxf(s[j][0], s[j][1]));
            mxb = fmaxf(mxb, fmaxf(s[j][2], s[j][3]));
        }
        mxa = fmaxf(mxa, __shfl_xor_sync(0xffffffffu, mxa, 1));
        mxa = fmaxf(mxa, __shfl_xor_sync(0xffffffffu, mxa, 2));
        mxb = fmaxf(mxb, __shfl_xor_sync(0xffffffffu, mxb, 1));
        mxb = fmaxf(mxb, __shfl_xor_sync(0xffffffffu, mxb, 2));

        float mna = fmaxf(m_a, mxa), mnb = fmaxf(m_b, mxb);
        float ca = fexp2(m_a - mna), cb2 = fexp2(m_b - mnb);
        m_a = mna; m_b = mnb;

        float sa = 0.0f, sbv = 0.0f;
        uint32_t ph[8][2], pl[8][2];
#pragma unroll
        for (int j = 0; j < 8; j++) {
            float p0 = fexp2(s[j][0] - mna);
            float p1 = fexp2(s[j][1] - mna);
            float p2 = fexp2(s[j][2] - mnb);
            float p3 = fexp2(s[j][3] - mnb);
            sa  += p0 + p1;
            sbv += p2 + p3;
            uint32_t h0 = pack2(p0, p1);
            uint32_t h1 = pack2(p2, p3);
            ph[j][0] = h0; ph[j][1] = h1;
            pl[j][0] = pack2(p0 - __int_as_float(h0 << 16),
                             p1 - __int_as_float(h0 & 0xffff0000u));
            pl[j][1] = pack2(p2 - __int_as_float(h1 << 16),
                             p3 - __int_as_float(h1 & 0xffff0000u));
        }
        sa  += __shfl_xor_sync(0xffffffffu, sa, 1);
        sa  += __shfl_xor_sync(0xffffffffu, sa, 2);
        sbv += __shfl_xor_sync(0xffffffffu, sbv, 1);
        sbv += __shfl_xor_sync(0xffffffffu, sbv, 2);
        l_a = l_a * ca + sa;
        l_b = l_b * cb2 + sbv;

#pragma unroll
        for (int ni = 0; ni < 16; ni++) {
            acc_o[ni][0] *= ca;  acc_o[ni][1] *= ca;
            acc_o[ni][2] *= cb2; acc_o[ni][3] *= cb2;
        }

        // ---- O += P V (bf16x3) ----
        const uint32_t vbh = kbase + 32768u;
        const uint32_t vbl = kbase + 49152u;
#pragma unroll
        for (int kc2 = 0; kc2 < 4; kc2++) {
            uint32_t aPh[4] = {ph[2 * kc2][0], ph[2 * kc2][1],
                               ph[2 * kc2 + 1][0], ph[2 * kc2 + 1][1]};
            uint32_t aPl[4] = {pl[2 * kc2][0], pl[2 * kc2][1],
                               pl[2 * kc2 + 1][0], pl[2 * kc2 + 1][1]};
            uint32_t vrow = (uint32_t)(kc2 * 16 + (lane & 15));
#pragma unroll
            for (int nd = 0; nd < 8; nd++) {
                uint32_t cb = (uint32_t)nd * 32 + chalf;
                uint32_t vh4[4], vl4[4];
                ldsm_x4t(vh4, vbh + fswz(vrow, cb));
                ldsm_x4t(vl4, vbl + fswz(vrow, cb));
                mma_bf16(acc_o[2 * nd],     aPh, vh4[0], vh4[1]);
                mma_bf16(acc_o[2 * nd],     aPh, vl4[0], vl4[1]);
                mma_bf16(acc_o[2 * nd],     aPl, vh4[0], vh4[1]);
                mma_bf16(acc_o[2 * nd + 1], aPh, vh4[2], vh4[3]);
                mma_bf16(acc_o[2 * nd + 1], aPh, vl4[2], vl4[3]);
                mma_bf16(acc_o[2 * nd + 1], aPl, vh4[2], vh4[3]);
            }
        }
    }

    // ---- epilogue: normalize, split to bf16 hi/lo, store ----
    float inva = __fdividef(1.0f, l_a);
    float invb = __fdividef(1.0f, l_b);
    int gr = lane >> 2, c2 = (lane & 3) * 2;
    size_t oa = (size_t)(b * SEQ + q0 + wr + gr) * DIMM + h * HDIM;
    size_t ob = oa + (size_t)8 * DIMM;
#pragma unroll
    for (int ni = 0; ni < 16; ni++) {
        int col = ni * 8 + c2;
        float f0 = acc_o[ni][0] * inva, f1 = acc_o[ni][1] * inva;
        uint32_t hA = pack2(f0, f1);
        uint32_t lA = pack2(f0 - __int_as_float(hA << 16),
                            f1 - __int_as_float(hA & 0xffff0000u));
        *(uint32_t*)&Ah[oa + col] = hA;
        *(uint32_t*)&Al[oa + col] = lA;
        float f2 = acc_o[ni][2] * invb, f3 = acc_o[ni][3] * invb;
        uint32_t hB = pack2(f2, f3);
        uint32_t lB = pack2(f2 - __int_as_float(hB << 16),
                            f3 - __int_as_float(hB & 0xffff0000u));
        *(uint32_t*)&Ah[ob + col] = hB;
        *(uint32_t*)&Al[ob + col] = lB;
    }
}

// ---------------------------------------------------------------------------
extern "C" void kernel_launch(void* const* d_in, const int* in_sizes, int n_in,
                              void* d_out, int out_size)
{
    const float* x  = (const float*)d_in[0];
    const float* Wq = (const float*)d_in[1];
    const float* bq = (const float*)d_in[2];
    const float* Wk = (const float*)d_in[3];
    const float* bk = (const float*)d_in[4];
    const float* Wv = (const float*)d_in[5];
    const float* bv = (const float*)d_in[6];
    const float* Wo = (const float*)d_in[7];
    const float* bo = (const float*)d_in[8];
    float* out = (float*)d_out;

    float *qp, *kp;
    __nv_bfloat16 *xh, *xl, *wh, *wl, *qh, *ql, *kh, *kl, *vh, *vl, *ah, *al;
    cudaGetSymbolAddress((void**)&qp, g_Q);
    cudaGetSymbolAddress((void**)&kp, g_K);
    cudaGetSymbolAddress((void**)&xh, g_xh);
    cudaGetSymbolAddress((void**)&xl, g_xl);
    cudaGetSymbolAddress((void**)&wh, g_Wh);
    cudaGetSymbolAddress((void**)&wl, g_Wl);
    cudaGetSymbolAddress((void**)&qh, g_Qh);
    cudaGetSymbolAddress((void**)&ql, g_Ql);
    cudaGetSymbolAddress((void**)&kh, g_Kh);
    cudaGetSymbolAddress((void**)&kl, g_Kl);
    cudaGetSymbolAddress((void**)&vh, g_Vh);
    cudaGetSymbolAddress((void**)&vl, g_Vl);
    cudaGetSymbolAddress((void**)&ah, g_Ah);
    cudaGetSymbolAddress((void**)&al, g_Al);

    cudaFuncSetAttribute(gemm_bf3,
                         cudaFuncAttributeMaxDynamicSharedMemorySize, GEMM_SMEM);
    cudaFuncSetAttribute(flash_tc,
                         cudaFuncAttributeMaxDynamicSharedMemorySize, FLASH_SMEM);

    const size_t WSZ = (size_t)DIMM * DIMM;
    const int NX = MTOK * DIMM;
    const int NW = DIMM * DIMM;

    split_kernel<<<NX / 4 / 256, 256>>>(x,  xh, xl, NX);
    split_kernel<<<NW / 4 / 256, 256>>>(Wq, wh + 0 * WSZ, wl + 0 * WSZ, NW);
    split_kernel<<<NW / 4 / 256, 256>>>(Wk, wh + 1 * WSZ, wl + 1 * WSZ, NW);
    split_kernel<<<NW / 4 / 256, 256>>>(Wv, wh + 2 * WSZ, wl + 2 * WSZ, NW);
    split_kernel<<<NW / 4 / 256, 256>>>(Wo, wh + 3 * WSZ, wl + 3 * WSZ, NW);

    dim3 gg(DIMM / 128, MTOK / 128);

    gemm_bf3<<<gg, 256, GEMM_SMEM>>>(xh, xl, wh + 0 * WSZ, wl + 0 * WSZ, bq, qp,
                                     nullptr, nullptr, MTOK, DIMM, DIMM);
    gemm_bf3<<<gg, 256, GEMM_SMEM>>>(xh, xl, wh + 1 * WSZ, wl + 1 * WSZ, bk, kp,
                                     nullptr, nullptr, MTOK, DIMM, DIMM);
    // V projection: bf16 hi/lo split epilogue straight into flash operands
    gemm_bf3<<<gg, 256, GEMM_SMEM>>>(xh, xl, wh + 2 * WSZ, wl + 2 * WSZ, bv,
                                     nullptr, vh, vl, MTOK, DIMM, DIMM);

    rope_table_kernel<<<(SEQ * 64) / 256, 256>>>();
    int npair = MTOK * DIMM / 2;
    rope_split_kernel<<<(npair + 255) / 256, 256>>>(qp, kp);

    flash_tc<<<dim3(SEQ / 128, BATCH * NHEAD), 256, FLASH_SMEM>>>(
        qh, ql, kh, kl, vh, vl, ah, al);

    gemm_bf3<<<gg, 256, GEMM_SMEM>>>(ah, al, wh + 3 * WSZ, wl + 3 * WSZ, bo, out,
                                     nullptr, nullptr, MTOK, DIMM, DIMM);
}

// round 10
// speedup vs baseline: 3.6099x; 1.0061x over previous
#include <cuda_runtime.h>
#include <cuda_bf16.h>
#include <math.h>
#include <stdint.h>

#define DIMM   2048
#define NHEAD  16
#define HDIM   128
#define SEQ    2048
#define BATCH  2
#define MTOK   (BATCH*SEQ)   // 4096 tokens
#define WSZ    ((size_t)DIMM * DIMM)

// ---------------------------------------------------------------------------
// Device-global scratch (no allocation allowed)
// ---------------------------------------------------------------------------
__device__ __nv_bfloat16 g_xh[(size_t)MTOK * DIMM];
__device__ __nv_bfloat16 g_xl[(size_t)MTOK * DIMM];
__device__ __nv_bfloat16 g_Wh[4][WSZ];
__device__ __nv_bfloat16 g_Wl[4][WSZ];
__device__ __nv_bfloat16 g_Qh[(size_t)MTOK * DIMM];
__device__ __nv_bfloat16 g_Ql[(size_t)MTOK * DIMM];
__device__ __nv_bfloat16 g_Kh[(size_t)MTOK * DIMM];
__device__ __nv_bfloat16 g_Kl[(size_t)MTOK * DIMM];
__device__ __nv_bfloat16 g_Vh[(size_t)MTOK * DIMM];
__device__ __nv_bfloat16 g_Vl[(size_t)MTOK * DIMM];
__device__ __nv_bfloat16 g_Ah[(size_t)MTOK * DIMM];
__device__ __nv_bfloat16 g_Al[(size_t)MTOK * DIMM];

__device__ float2 g_rt[SEQ * 64];   // RoPE cos/sin table

// ---------------------------------------------------------------------------
// PTX helpers
// ---------------------------------------------------------------------------
__device__ __forceinline__ uint32_t sm_u32(const void* p) {
    return (uint32_t)__cvta_generic_to_shared(p);
}
__device__ __forceinline__ void cp16(uint32_t dst, const void* src) {
    asm volatile("cp.async.cg.shared.global [%0], [%1], 16;" :: "r"(dst), "l"(src) : "memory");
}
__device__ __forceinline__ void ldsm_x4(uint32_t* r, uint32_t a) {
    asm volatile("ldmatrix.sync.aligned.m8n8.x4.shared.b16 {%0,%1,%2,%3}, [%4];"
                 : "=r"(r[0]), "=r"(r[1]), "=r"(r[2]), "=r"(r[3]) : "r"(a));
}
__device__ __forceinline__ void ldsm_x4t(uint32_t* r, uint32_t a) {
    asm volatile("ldmatrix.sync.aligned.m8n8.x4.trans.shared.b16 {%0,%1,%2,%3}, [%4];"
                 : "=r"(r[0]), "=r"(r[1]), "=r"(r[2]), "=r"(r[3]) : "r"(a));
}
__device__ __forceinline__ void mma_bf16(float* c, const uint32_t* a,
                                         uint32_t b0, uint32_t b1) {
    asm volatile(
        "mma.sync.aligned.m16n8k16.row.col.f32.bf16.bf16.f32 "
        "{%0,%1,%2,%3}, {%4,%5,%6,%7}, {%8,%9}, {%0,%1,%2,%3};"
        : "+f"(c[0]), "+f"(c[1]), "+f"(c[2]), "+f"(c[3])
        : "r"(a[0]), "r"(a[1]), "r"(a[2]), "r"(a[3]), "r"(b0), "r"(b1));
}
// pack2(lo, hi): bf16x2 with lo in lower half
__device__ __forceinline__ uint32_t pack2(float lo, float hi) {
    uint32_t r;
    asm("cvt.rn.bf16x2.f32 %0, %1, %2;" : "=r"(r) : "f"(hi), "f"(lo));
    return r;
}
__device__ __forceinline__ float fexp2(float x) {
    float y;
    asm("ex2.approx.ftz.f32 %0, %1;" : "=f"(y) : "f"(x));
    return y;
}

extern __shared__ __nv_bfloat16 gsm[];

// ---------------------------------------------------------------------------
// Split fp32 -> bf16 hi + lo
// ---------------------------------------------------------------------------
__global__ __launch_bounds__(256) void split_kernel(
    const float* __restrict__ src, __nv_bfloat16* __restrict__ hi,
    __nv_bfloat16* __restrict__ lo, int n)
{
    int i = (blockIdx.x * blockDim.x + threadIdx.x) * 4;
    if (i >= n) return;
    float4 v = *(const float4*)(src + i);
    float vs[4] = {v.x, v.y, v.z, v.w};
#pragma unroll
    for (int j = 0; j < 4; j += 2) {
        uint32_t h = pack2(vs[j], vs[j + 1]);
        uint32_t l = pack2(vs[j] - __int_as_float(h << 16),
                           vs[j + 1] - __int_as_float(h & 0xffff0000u));
        *(uint32_t*)(hi + i + j) = h;
        *(uint32_t*)(lo + i + j) = l;
    }
}

// ---------------------------------------------------------------------------
// RoPE table (double precision)
// ---------------------------------------------------------------------------
__global__ __launch_bounds__(256) void rope_table_kernel()
{
    int idx = blockIdx.x * blockDim.x + threadIdx.x;
    if (idx >= SEQ * 64) return;
    int pos = idx >> 6, i = idx & 63;
    double invf = pow(10000.0, -(double)i / 64.0);
    double sd, cd;
    sincos((double)pos * invf, &sd, &cd);
    g_rt[idx] = make_float2((float)cd, (float)sd);
}

// ---------------------------------------------------------------------------
// bf16x3 GEMM v2 (legacy mma): CTA tile 128x256, BK=32, 8 warps of 64x64,
// 4-stage cp.async pipeline.  B = W [K,N] row-major (ldsm trans).
// job==1 (QKV fused): blockIdx.x selects region (Q/K/V); epilogue fuses
//   bias + (rope [+qscale]) + bf16 hi/lo split into g_{Q,K,V}{h,l}.
// job==0 (O): bias + fp32 store to `out`.
// ---------------------------------------------------------------------------
#define SAH 0
#define SAL 5120
#define SBH 10240
#define SBL 18688
#define ST2_SZ 27136               // bf16 elems per stage
#define NSTG 4
#define GM2_SMEM (NSTG * ST2_SZ * 2)   // 217088 bytes

__global__ __launch_bounds__(256) void tc2_gemm(
    const __nv_bfloat16* __restrict__ Ahg, const __nv_bfloat16* __restrict__ Alg,
    const __nv_bfloat16* __restrict__ Wh0, const __nv_bfloat16* __restrict__ Wl0,
    const float* __restrict__ bq, const float* __restrict__ bk,
    const float* __restrict__ bv, const float* __restrict__ bo,
    float* __restrict__ out, int job)
{
    const int tid  = threadIdx.x;
    const int lane = tid & 31;
    const int wid  = tid >> 5;
    const int wm   = (wid >> 2) * 64;
    const int wn   = (wid & 3) * 64;
    const int bm   = blockIdx.y * 128;
    const int bn   = blockIdx.x * 256;

    int region, bnl, mode;
    if (job == 1) {
        region = bn >> 11;
        bnl    = bn & 2047;
        mode   = (region == 0) ? 2 : (region == 1) ? 3 : 1;
    } else {
        region = 3; bnl = bn; mode = 0;
    }
    const __nv_bfloat16* Bhg = Wh0 + (size_t)region * WSZ;
    const __nv_bfloat16* Blg = Wl0 + (size_t)region * WSZ;
    const float* bias = (job == 0) ? bo : (region == 0) ? bq
                        : (region == 1) ? bk : bv;

    auto load_stage = [&](int s, int k0) {
        __nv_bfloat16* S = gsm + s * ST2_SZ;
#pragma unroll
        for (int c = tid; c < 512; c += 256) {
            int row = c >> 2, ch = (c & 3) * 8;
            size_t aoff = (size_t)(bm + row) * DIMM + k0 + ch;
            cp16(sm_u32(S + SAH + row * 40 + ch), Ahg + aoff);
            cp16(sm_u32(S + SAL + row * 40 + ch), Alg + aoff);
        }
#pragma unroll
        for (int c = tid; c < 1024; c += 256) {
            int row = c >> 5, nc = (c & 31) * 8;
            size_t boff = (size_t)(k0 + row) * DIMM + bnl + nc;
            cp16(sm_u32(S + SBH + row * 264 + nc), Bhg + boff);
            cp16(sm_u32(S + SBL + row * 264 + nc), Blg + boff);
        }
    };

    float acc[4][8][4];
#pragma unroll
    for (int mi = 0; mi < 4; mi++)
#pragma unroll
        for (int ni = 0; ni < 8; ni++)
#pragma unroll
            for (int e = 0; e < 4; e++) acc[mi][ni][e] = 0.0f;

    const int NT = DIMM / 32;   // 64
    load_stage(0, 0);  asm volatile("cp.async.commit_group;" ::: "memory");
    load_stage(1, 32); asm volatile("cp.async.commit_group;" ::: "memory");
    load_stage(2, 64); asm volatile("cp.async.commit_group;" ::: "memory");

    for (int it = 0; it < NT; it++) {
        asm volatile("cp.async.wait_group 2;" ::: "memory");
        __syncthreads();
        // prefetch (always commit to keep wait_group bookkeeping exact)
        if (it + 3 < NT) load_stage((it + 3) & 3, (it + 3) * 32);
        asm volatile("cp.async.commit_group;" ::: "memory");

        const __nv_bfloat16* S = gsm + (it & 3) * ST2_SZ;
#pragma unroll
        for (int ks = 0; ks < 2; ks++) {
            uint32_t ah[4][4], al[4][4];
            const int arow = lane & 15;
            const int acol = ks * 16 + (lane >> 4) * 8;
#pragma unroll
            for (int mi = 0; mi < 4; mi++) {
                const __nv_bfloat16* pa = S + SAH + (wm + mi * 16 + arow) * 40 + acol;
                ldsm_x4(ah[mi], sm_u32(pa));
                ldsm_x4(al[mi], sm_u32(pa + (SAL - SAH)));
            }
            const int brow = ks * 16 + (lane & 15);
#pragma unroll
            for (int half = 0; half < 2; half++) {
                uint32_t bh[2][4], bl[2][4];
#pragma unroll
                for (int np = 0; np < 2; np++) {
                    int bcol = wn + (half * 2 + np) * 16 + (lane >> 4) * 8;
                    const __nv_bfloat16* pb = S + SBH + brow * 264 + bcol;
                    ldsm_x4t(bh[np], sm_u32(pb));
                    ldsm_x4t(bl[np], sm_u32(pb + (SBL - SBH)));
                }
#pragma unroll
                for (int mi = 0; mi < 4; mi++) {
#pragma unroll
                    for (int n4 = 0; n4 < 4; n4++) {
                        float* c = acc[mi][half * 4 + n4];
                        uint32_t h0 = bh[n4 >> 1][(n4 & 1) * 2];
                        uint32_t h1 = bh[n4 >> 1][(n4 & 1) * 2 + 1];
                        uint32_t l0 = bl[n4 >> 1][(n4 & 1) * 2];
                        uint32_t l1 = bl[n4 >> 1][(n4 & 1) * 2 + 1];
                        mma_bf16(c, ah[mi], h0, h1);
                        mma_bf16(c, ah[mi], l0, l1);
                        mma_bf16(c, al[mi], h0, h1);
                    }
                }
            }
        }
        __syncthreads();
    }

    // ---- epilogue ----
    __nv_bfloat16* Dh = (region == 0) ? g_Qh : (region == 1) ? g_Kh : g_Vh;
    __nv_bfloat16* Dl = (region == 0) ? g_Ql : (region == 1) ? g_Kl : g_Vl;
    const float QS = 1.4426950408889634f / 128.0f;

#pragma unroll
    for (int mi = 0; mi < 4; mi++) {
#pragma unroll
        for (int ni = 0; ni < 8; ni++) {
            int row0 = bm + wm + mi * 16 + (lane >> 2);
            int colL = bnl + wn + ni * 8 + (lane & 3) * 2;
            float2 bb = *(const float2*)(bias + colL);
            float f0 = acc[mi][ni][0] + bb.x, f1 = acc[mi][ni][1] + bb.y;
            float f2 = acc[mi][ni][2] + bb.x, f3 = acc[mi][ni][3] + bb.y;
            if (mode == 0) {
                *(float2*)(out + (size_t)row0 * DIMM + colL)       = make_float2(f0, f1);
                *(float2*)(out + (size_t)(row0 + 8) * DIMM + colL) = make_float2(f2, f3);
            } else {
                if (mode >= 2) {
                    int i = (colL & 127) >> 1;
                    float2 cs0 = g_rt[(row0 & (SEQ - 1)) * 64 + i];
                    float2 cs1 = g_rt[((row0 + 8) & (SEQ - 1)) * 64 + i];
                    float t0 = f0 * cs0.x - f1 * cs0.y;
                    float t1 = f1 * cs0.x + f0 * cs0.y;
                    float t2 = f2 * cs1.x - f3 * cs1.y;
                    float t3 = f3 * cs1.x + f2 * cs1.y;
                    if (mode == 2) { t0 *= QS; t1 *= QS; t2 *= QS; t3 *= QS; }
                    f0 = t0; f1 = t1; f2 = t2; f3 = t3;
                }
                uint32_t h0 = pack2(f0, f1);
                uint32_t l0 = pack2(f0 - __int_as_float(h0 << 16),
                                    f1 - __int_as_float(h0 & 0xffff0000u));
                uint32_t h1 = pack2(f2, f3);
                uint32_t l1 = pack2(f2 - __int_as_float(h1 << 16),
                                    f3 - __int_as_float(h1 & 0xffff0000u));
                *(uint32_t*)(Dh + (size_t)row0 * DIMM + colL)       = h0;
                *(uint32_t*)(Dl + (size_t)row0 * DIMM + colL)       = l0;
                *(uint32_t*)(Dh + (size_t)(row0 + 8) * DIMM + colL) = h1;
                *(uint32_t*)(Dl + (size_t)(row0 + 8) * DIMM + colL) = l1;
            }
        }
    }
}

// ---------------------------------------------------------------------------
// Tensor-core flash attention (bf16x3) — unchanged from R7 passing kernel.
// ---------------------------------------------------------------------------
#define FQH 0u
#define FQL 32768u
#define FST(s) (65536u + (uint32_t)(s) * 65536u)
#define FLASH_SMEM 196608

__device__ __forceinline__ uint32_t fswz(uint32_t row, uint32_t colbyte) {
    uint32_t off = row * 256u + colbyte;
    return off ^ ((row & 7u) << 4);
}

__device__ __forceinline__ void flash_load_kv(
    uint32_t sb, int stage, size_t kb,
    const __nv_bfloat16* __restrict__ Kh_, const __nv_bfloat16* __restrict__ Kl_,
    const __nv_bfloat16* __restrict__ Vh_, const __nv_bfloat16* __restrict__ Vl_,
    int tid)
{
    uint32_t base = sb + FST(stage);
#pragma unroll
    for (int c = tid; c < 1024; c += 256) {
        uint32_t row = c >> 4, ch = c & 15;
        uint32_t d = fswz(row, ch * 16);
        size_t so = kb + (size_t)row * DIMM + ch * 8;
        cp16(base + d,          Kh_ + so);
        cp16(base + 16384u + d, Kl_ + so);
        cp16(base + 32768u + d, Vh_ + so);
        cp16(base + 49152u + d, Vl_ + so);
    }
}

__global__ __launch_bounds__(256) void flash_tc(
    const __nv_bfloat16* __restrict__ Qh_, const __nv_bfloat16* __restrict__ Ql_,
    const __nv_bfloat16* __restrict__ Kh_, const __nv_bfloat16* __restrict__ Kl_,
    const __nv_bfloat16* __restrict__ Vh_, const __nv_bfloat16* __restrict__ Vl_,
    __nv_bfloat16* __restrict__ Ah, __nv_bfloat16* __restrict__ Al)
{
    const uint32_t sb = sm_u32(gsm);
    const int tid  = threadIdx.x;
    const int lane = tid & 31;
    const int wid  = tid >> 5;
    const int wr   = wid * 16;
    const int bh   = blockIdx.y;
    const int b    = bh >> 4;
    const int h    = bh & 15;
    const int q0   = blockIdx.x * 128;

    const size_t qg = (size_t)(b * SEQ + q0) * DIMM + h * HDIM;
    const size_t kg0 = (size_t)(b * SEQ) * DIMM + h * HDIM;

#pragma unroll
    for (int c = tid; c < 2048; c += 256) {
        uint32_t row = c >> 4, ch = c & 15;
        uint32_t d = fswz(row, ch * 16);
        size_t so = qg + (size_t)row * DIMM + ch * 8;
        cp16(sb + FQH + d, Qh_ + so);
        cp16(sb + FQL + d, Ql_ + so);
    }
    flash_load_kv(sb, 0, kg0, Kh_, Kl_, Vh_, Vl_, tid);
    asm volatile("cp.async.commit_group;" ::: "memory");

    float acc_o[16][4];
#pragma unroll
    for (int ni = 0; ni < 16; ni++)
#pragma unroll
        for (int e = 0; e < 4; e++) acc_o[ni][e] = 0.0f;
    float m_a = -INFINITY, m_b = -INFINITY, l_a = 0.0f, l_b = 0.0f;

    const uint32_t arow = (uint32_t)(wr + (lane & 15));
    const uint32_t chalf = (uint32_t)((lane >> 4) * 16);

    for (int kt = 0; kt < SEQ / 64; kt++) {
        asm volatile("cp.async.wait_group 0;" ::: "memory");
        __syncthreads();
        if (kt + 1 < SEQ / 64) {
            flash_load_kv(sb, (kt + 1) & 1, kg0 + (size_t)(kt + 1) * 64 * DIMM,
                          Kh_, Kl_, Vh_, Vl_, tid);
            asm volatile("cp.async.commit_group;" ::: "memory");
        }
        const uint32_t kbase = sb + FST(kt & 1);

        float s[8][4];
#pragma unroll
        for (int j = 0; j < 8; j++)
#pragma unroll
            for (int e = 0; e < 4; e++) s[j][e] = 0.0f;

#pragma unroll
        for (int kc = 0; kc < 8; kc++) {
            uint32_t cb = (uint32_t)kc * 32 + chalf;
            uint32_t aq[4], aql[4];
            ldsm_x4(aq,  sb + FQH + fswz(arow, cb));
            ldsm_x4(aql, sb + FQL + fswz(arow, cb));
#pragma unroll
            for (int g = 0; g < 4; g++) {
                uint32_t krow = (uint32_t)(g * 16 + (lane & 15));
                uint32_t kh4[4], kl4[4];
                ldsm_x4(kh4, kbase + fswz(krow, cb));
                ldsm_x4(kl4, kbase + 16384u + fswz(krow, cb));
                mma_bf16(s[2 * g],     aq,  kh4[0], kh4[2]);
                mma_bf16(s[2 * g],     aq,  kl4[0], kl4[2]);
                mma_bf16(s[2 * g],     aql, kh4[0], kh4[2]);
                mma_bf16(s[2 * g + 1], aq,  kh4[1], kh4[3]);
                mma_bf16(s[2 * g + 1], aq,  kl4[1], kl4[3]);
                mma_bf16(s[2 * g + 1], aql, kh4[1], kh4[3]);
            }
        }

        float mxa = -INFINITY, mxb = -INFINITY;
#pragma unroll
        for (int j = 0; j < 8; j++) {
            mxa = fmaxf(mxa, fmaxf(s[j][0], s[j][1]));
            mxb = fmaxf(mxb, fmaxf(s[j][2], s[j][3]));
        }
        mxa = fmaxf(mxa, __shfl_xor_sync(0xffffffffu, mxa, 1));
        mxa = fmaxf(mxa, __shfl_xor_sync(0xffffffffu, mxa, 2));
        mxb = fmaxf(mxb, __shfl_xor_sync(0xffffffffu, mxb, 1));
        mxb = fmaxf(mxb, __shfl_xor_sync(0xffffffffu, mxb, 2));

        float mna = fmaxf(m_a, mxa), mnb = fmaxf(m_b, mxb);
        float ca = fexp2(m_a - mna), cb2 = fexp2(m_b - mnb);
        m_a = mna; m_b = mnb;

        float sa = 0.0f, sbv = 0.0f;
        uint32_t ph[8][2], pl[8][2];
#pragma unroll
        for (int j = 0; j < 8; j++) {
            float p0 = fexp2(s[j][0] - mna);
            float p1 = fexp2(s[j][1] - mna);
            float p2 = fexp2(s[j][2] - mnb);
            float p3 = fexp2(s[j][3] - mnb);
            sa  += p0 + p1;
            sbv += p2 + p3;
            uint32_t h0 = pack2(p0, p1);
            uint32_t h1 = pack2(p2, p3);
            ph[j][0] = h0; ph[j][1] = h1;
            pl[j][0] = pack2(p0 - __int_as_float(h0 << 16),
                             p1 - __int_as_float(h0 & 0xffff0000u));
            pl[j][1] = pack2(p2 - __int_as_float(h1 << 16),
                             p3 - __int_as_float(h1 & 0xffff0000u));
        }
        sa  += __shfl_xor_sync(0xffffffffu, sa, 1);
        sa  += __shfl_xor_sync(0xffffffffu, sa, 2);
        sbv += __shfl_xor_sync(0xffffffffu, sbv, 1);
        sbv += __shfl_xor_sync(0xffffffffu, sbv, 2);
        l_a = l_a * ca + sa;
        l_b = l_b * cb2 + sbv;

#pragma unroll
        for (int ni = 0; ni < 16; ni++) {
            acc_o[ni][0] *= ca;  acc_o[ni][1] *= ca;
            acc_o[ni][2] *= cb2; acc_o[ni][3] *= cb2;
        }

        const uint32_t vbh = kbase + 32768u;
        const uint32_t vbl = kbase + 49152u;
#pragma unroll
        for (int kc2 = 0; kc2 < 4; kc2++) {
            uint32_t aPh[4] = {ph[2 * kc2][0], ph[2 * kc2][1],
                               ph[2 * kc2 + 1][0], ph[2 * kc2 + 1][1]};
            uint32_t aPl[4] = {pl[2 * kc2][0], pl[2 * kc2][1],
                               pl[2 * kc2 + 1][0], pl[2 * kc2 + 1][1]};
            uint32_t vrow = (uint32_t)(kc2 * 16 + (lane & 15));
#pragma unroll
            for (int nd = 0; nd < 8; nd++) {
                uint32_t cb = (uint32_t)nd * 32 + chalf;
                uint32_t vh4[4], vl4[4];
                ldsm_x4t(vh4, vbh + fswz(vrow, cb));
                ldsm_x4t(vl4, vbl + fswz(vrow, cb));
                mma_bf16(acc_o[2 * nd],     aPh, vh4[0], vh4[1]);
                mma_bf16(acc_o[2 * nd],     aPh, vl4[0], vl4[1]);
                mma_bf16(acc_o[2 * nd],     aPl, vh4[0], vh4[1]);
                mma_bf16(acc_o[2 * nd + 1], aPh, vh4[2], vh4[3]);
                mma_bf16(acc_o[2 * nd + 1], aPh, vl4[2], vl4[3]);
                mma_bf16(acc_o[2 * nd + 1], aPl, vh4[2], vh4[3]);
            }
        }
    }

    float inva = __fdividef(1.0f, l_a);
    float invb = __fdividef(1.0f, l_b);
    int gr = lane >> 2, c2 = (lane & 3) * 2;
    size_t oa = (size_t)(b * SEQ + q0 + wr + gr) * DIMM + h * HDIM;
    size_t ob = oa + (size_t)8 * DIMM;
#pragma unroll
    for (int ni = 0; ni < 16; ni++) {
        int col = ni * 8 + c2;
        float f0 = acc_o[ni][0] * inva, f1 = acc_o[ni][1] * inva;
        uint32_t hA = pack2(f0, f1);
        uint32_t lA = pack2(f0 - __int_as_float(hA << 16),
                            f1 - __int_as_float(hA & 0xffff0000u));
        *(uint32_t*)&Ah[oa + col] = hA;
        *(uint32_t*)&Al[oa + col] = lA;
        float f2 = acc_o[ni][2] * invb, f3 = acc_o[ni][3] * invb;
        uint32_t hB = pack2(f2, f3);
        uint32_t lB = pack2(f2 - __int_as_float(hB << 16),
                            f3 - __int_as_float(hB & 0xffff0000u));
        *(uint32_t*)&Ah[ob + col] = hB;
        *(uint32_t*)&Al[ob + col] = lB;
    }
}

// ---------------------------------------------------------------------------
extern "C" void kernel_launch(void* const* d_in, const int* in_sizes, int n_in,
                              void* d_out, int out_size)
{
    const float* x  = (const float*)d_in[0];
    const float* Wq = (const float*)d_in[1];
    const float* bq = (const float*)d_in[2];
    const float* Wk = (const float*)d_in[3];
    const float* bk = (const float*)d_in[4];
    const float* Wv = (const float*)d_in[5];
    const float* bv = (const float*)d_in[6];
    const float* Wo = (const float*)d_in[7];
    const float* bo = (const float*)d_in[8];
    float* out = (float*)d_out;

    __nv_bfloat16 *xh, *xl, *wh, *wl, *qh, *ql, *kh, *kl, *vh, *vl, *ah, *al;
    cudaGetSymbolAddress((void**)&xh, g_xh);
    cudaGetSymbolAddress((void**)&xl, g_xl);
    cudaGetSymbolAddress((void**)&wh, g_Wh);
    cudaGetSymbolAddress((void**)&wl, g_Wl);
    cudaGetSymbolAddress((void**)&qh, g_Qh);
    cudaGetSymbolAddress((void**)&ql, g_Ql);
    cudaGetSymbolAddress((void**)&kh, g_Kh);
    cudaGetSymbolAddress((void**)&kl, g_Kl);
    cudaGetSymbolAddress((void**)&vh, g_Vh);
    cudaGetSymbolAddress((void**)&vl, g_Vl);
    cudaGetSymbolAddress((void**)&ah, g_Ah);
    cudaGetSymbolAddress((void**)&al, g_Al);

    cudaFuncSetAttribute(tc2_gemm,
                         cudaFuncAttributeMaxDynamicSharedMemorySize, GM2_SMEM);
    cudaFuncSetAttribute(flash_tc,
                         cudaFuncAttributeMaxDynamicSharedMemorySize, FLASH_SMEM);

    const int NX = MTOK * DIMM;
    const int NW = DIMM * DIMM;

    split_kernel<<<NX / 4 / 256, 256>>>(x,  xh, xl, NX);
    split_kernel<<<NW / 4 / 256, 256>>>(Wq, wh + 0 * WSZ, wl + 0 * WSZ, NW);
    split_kernel<<<NW / 4 / 256, 256>>>(Wk, wh + 1 * WSZ, wl + 1 * WSZ, NW);
    split_kernel<<<NW / 4 / 256, 256>>>(Wv, wh + 2 * WSZ, wl + 2 * WSZ, NW);
    split_kernel<<<NW / 4 / 256, 256>>>(Wo, wh + 3 * WSZ, wl + 3 * WSZ, NW);
    rope_table_kernel<<<(SEQ * 64) / 256, 256>>>();

    // Fused Q/K/V projection + bias + RoPE + hi/lo split
    tc2_gemm<<<dim3(3 * DIMM / 256, MTOK / 128), 256, GM2_SMEM>>>(
        xh, xl, wh, wl, bq, bk, bv, bo, nullptr, 1);

    flash_tc<<<dim3(SEQ / 128, BATCH * NHEAD), 256, FLASH_SMEM>>>(
        qh, ql, kh, kl, vh, vl, ah, al);

    // Output projection (fp32 + bias)
    tc2_gemm<<<dim3(DIMM / 256, MTOK / 128), 256, GM2_SMEM>>>(
        ah, al, wh, wl, bq, bk, bv, bo, out, 0);
}

// round 11
// speedup vs baseline: 5.0946x; 1.4113x over previous
#include <cuda_runtime.h>
#include <cuda_fp16.h>
#include <math.h>
#include <stdint.h>

#define DIMM   2048
#define NHEAD  16
#define HDIM   128
#define SEQ    2048
#define BATCH  2
#define MTOK   (BATCH*SEQ)   // 4096 tokens
#define WSZ    ((size_t)DIMM * DIMM)

// ---------------------------------------------------------------------------
// Device-global scratch (no allocation allowed)
// ---------------------------------------------------------------------------
__device__ __half g_xh[(size_t)MTOK * DIMM];
__device__ __half g_xl[(size_t)MTOK * DIMM];
__device__ __half g_W[4][WSZ];                 // weights, fp16 hi only
__device__ __half g_Qh[(size_t)MTOK * DIMM];
__device__ __half g_Ql[(size_t)MTOK * DIMM];
__device__ __half g_Kh[(size_t)MTOK * DIMM];   // fp16 only
__device__ __half g_Vh[(size_t)MTOK * DIMM];   // fp16 only
__device__ __half g_Ah[(size_t)MTOK * DIMM];
__device__ __half g_Al[(size_t)MTOK * DIMM];

__device__ float2 g_rt[SEQ * 64];   // RoPE cos/sin table

// ---------------------------------------------------------------------------
// PTX helpers
// ---------------------------------------------------------------------------
__device__ __forceinline__ uint32_t sm_u32(const void* p) {
    return (uint32_t)__cvta_generic_to_shared(p);
}
__device__ __forceinline__ void cp16(uint32_t dst, const void* src) {
    asm volatile("cp.async.cg.shared.global [%0], [%1], 16;" :: "r"(dst), "l"(src) : "memory");
}
__device__ __forceinline__ void ldsm_x4(uint32_t* r, uint32_t a) {
    asm volatile("ldmatrix.sync.aligned.m8n8.x4.shared.b16 {%0,%1,%2,%3}, [%4];"
                 : "=r"(r[0]), "=r"(r[1]), "=r"(r[2]), "=r"(r[3]) : "r"(a));
}
__device__ __forceinline__ void ldsm_x4t(uint32_t* r, uint32_t a) {
    asm volatile("ldmatrix.sync.aligned.m8n8.x4.trans.shared.b16 {%0,%1,%2,%3}, [%4];"
                 : "=r"(r[0]), "=r"(r[1]), "=r"(r[2]), "=r"(r[3]) : "r"(a));
}
__device__ __forceinline__ void mma_f16(float* c, const uint32_t* a,
                                        uint32_t b0, uint32_t b1) {
    asm volatile(
        "mma.sync.aligned.m16n8k16.row.col.f32.f16.f16.f32 "
        "{%0,%1,%2,%3}, {%4,%5,%6,%7}, {%8,%9}, {%0,%1,%2,%3};"
        : "+f"(c[0]), "+f"(c[1]), "+f"(c[2]), "+f"(c[3])
        : "r"(a[0]), "r"(a[1]), "r"(a[2]), "r"(a[3]), "r"(b0), "r"(b1));
}
__device__ __forceinline__ float fexp2(float x) {
    float y;
    asm("ex2.approx.ftz.f32 %0, %1;" : "=f"(y) : "f"(x));
    return y;
}
// pack two floats to f16x2 (f0 in low half); also return residuals
__device__ __forceinline__ uint32_t packh2(float f0, float f1) {
    __half2 h = __floats2half2_rn(f0, f1);
    return *(uint32_t*)&h;
}
__device__ __forceinline__ void split2h(float f0, float f1,
                                        uint32_t& hi, uint32_t& lo) {
    __half2 h = __floats2half2_rn(f0, f1);
    float2 fb = __half22float2(h);
    __half2 l = __floats2half2_rn(f0 - fb.x, f1 - fb.y);
    hi = *(uint32_t*)&h;
    lo = *(uint32_t*)&l;
}

extern __shared__ __half gsm[];

// ---------------------------------------------------------------------------
// Split fp32 -> fp16 hi + lo (for x)
// ---------------------------------------------------------------------------
__global__ __launch_bounds__(256) void split_kernel(
    const float* __restrict__ src, __half* __restrict__ hi,
    __half* __restrict__ lo, int n)
{
    int i = (blockIdx.x * blockDim.x + threadIdx.x) * 4;
    if (i >= n) return;
    float4 v = *(const float4*)(src + i);
    float vs[4] = {v.x, v.y, v.z, v.w};
#pragma unroll
    for (int j = 0; j < 4; j += 2) {
        uint32_t h, l;
        split2h(vs[j], vs[j + 1], h, l);
        *(uint32_t*)(hi + i + j) = h;
        *(uint32_t*)(lo + i + j) = l;
    }
}

// ---------------------------------------------------------------------------
// Convert fp32 -> fp16 (for W)
// ---------------------------------------------------------------------------
__global__ __launch_bounds__(256) void convert_kernel(
    const float* __restrict__ src, __half* __restrict__ dst, int n)
{
    int i = (blockIdx.x * blockDim.x + threadIdx.x) * 4;
    if (i >= n) return;
    float4 v = *(const float4*)(src + i);
    *(uint32_t*)(dst + i)     = packh2(v.x, v.y);
    *(uint32_t*)(dst + i + 2) = packh2(v.z, v.w);
}

// ---------------------------------------------------------------------------
// RoPE table (double precision)
// ---------------------------------------------------------------------------
__global__ __launch_bounds__(256) void rope_table_kernel()
{
    int idx = blockIdx.x * blockDim.x + threadIdx.x;
    if (idx >= SEQ * 64) return;
    int pos = idx >> 6, i = idx & 63;
    double invf = pow(10000.0, -(double)i / 64.0);
    double sd, cd;
    sincos((double)pos * invf, &sd, &cd);
    g_rt[idx] = make_float2((float)cd, (float)sd);
}

// ---------------------------------------------------------------------------
// fp16x2 GEMM (2 mma: hh + lh): CTA 128x256, BK=32, 8 warps of 64x64,
// 4-stage cp.async.  A = x (hi+lo fp16), B = W fp16 row-major (ldsm trans).
// job==1 (QKV fused): blockIdx.x selects region; epilogue:
//   region 0 (Q): bias + rope + qscale + fp16 hi/lo split
//   region 1 (K): bias + rope + fp16
//   region 2 (V): bias + fp16
// job==0 (O): bias + fp32 store.
// ---------------------------------------------------------------------------
#define SAH 0
#define SAL 5120
#define SBH 10240
#define ST3_SZ 18688               // fp16 elems per stage (37376 B)
#define NSTG 4
#define GM3_SMEM (NSTG * ST3_SZ * 2)   // 149504 bytes

__global__ __launch_bounds__(256) void tc3_gemm(
    const __half* __restrict__ Ahg, const __half* __restrict__ Alg,
    const __half* __restrict__ W0,
    const float* __restrict__ bq, const float* __restrict__ bk,
    const float* __restrict__ bv, const float* __restrict__ bo,
    float* __restrict__ out, int job)
{
    const int tid  = threadIdx.x;
    const int lane = tid & 31;
    const int wid  = tid >> 5;
    const int wm   = (wid >> 2) * 64;
    const int wn   = (wid & 3) * 64;
    const int bm   = blockIdx.y * 128;
    const int bn   = blockIdx.x * 256;

    int region, bnl;
    if (job == 1) { region = bn >> 11; bnl = bn & 2047; }
    else          { region = 3;        bnl = bn; }
    const __half* Bhg = W0 + (size_t)region * WSZ;
    const float* bias = (job == 0) ? bo : (region == 0) ? bq
                        : (region == 1) ? bk : bv;

    auto load_stage = [&](int s, int k0) {
        __half* S = gsm + s * ST3_SZ;
#pragma unroll
        for (int c = tid; c < 512; c += 256) {
            int row = c >> 2, ch = (c & 3) * 8;
            size_t aoff = (size_t)(bm + row) * DIMM + k0 + ch;
            cp16(sm_u32(S + SAH + row * 40 + ch), Ahg + aoff);
            cp16(sm_u32(S + SAL + row * 40 + ch), Alg + aoff);
        }
#pragma unroll
        for (int c = tid; c < 1024; c += 256) {
            int row = c >> 5, nc = (c & 31) * 8;
            size_t boff = (size_t)(k0 + row) * DIMM + bnl + nc;
            cp16(sm_u32(S + SBH + row * 264 + nc), Bhg + boff);
        }
    };

    float acc[4][8][4];
#pragma unroll
    for (int mi = 0; mi < 4; mi++)
#pragma unroll
        for (int ni = 0; ni < 8; ni++)
#pragma unroll
            for (int e = 0; e < 4; e++) acc[mi][ni][e] = 0.0f;

    const int NT = DIMM / 32;   // 64
    load_stage(0, 0);  asm volatile("cp.async.commit_group;" ::: "memory");
    load_stage(1, 32); asm volatile("cp.async.commit_group;" ::: "memory");
    load_stage(2, 64); asm volatile("cp.async.commit_group;" ::: "memory");

    for (int it = 0; it < NT; it++) {
        asm volatile("cp.async.wait_group 2;" ::: "memory");
        __syncthreads();
        if (it + 3 < NT) load_stage((it + 3) & 3, (it + 3) * 32);
        asm volatile("cp.async.commit_group;" ::: "memory");

        const __half* S = gsm + (it & 3) * ST3_SZ;
#pragma unroll
        for (int ks = 0; ks < 2; ks++) {
            uint32_t ah[4][4], al[4][4];
            const int arow = lane & 15;
            const int acol = ks * 16 + (lane >> 4) * 8;
#pragma unroll
            for (int mi = 0; mi < 4; mi++) {
                const __half* pa = S + SAH + (wm + mi * 16 + arow) * 40 + acol;
                ldsm_x4(ah[mi], sm_u32(pa));
                ldsm_x4(al[mi], sm_u32(pa + (SAL - SAH)));
            }
            const int brow = ks * 16 + (lane & 15);
#pragma unroll
            for (int half = 0; half < 2; half++) {
                uint32_t bh[2][4];
#pragma unroll
                for (int np = 0; np < 2; np++) {
                    int bcol = wn + (half * 2 + np) * 16 + (lane >> 4) * 8;
                    ldsm_x4t(bh[np], sm_u32(S + SBH + brow * 264 + bcol));
                }
#pragma unroll
                for (int mi = 0; mi < 4; mi++) {
#pragma unroll
                    for (int n4 = 0; n4 < 4; n4++) {
                        float* c = acc[mi][half * 4 + n4];
                        uint32_t b0 = bh[n4 >> 1][(n4 & 1) * 2];
                        uint32_t b1 = bh[n4 >> 1][(n4 & 1) * 2 + 1];
                        mma_f16(c, ah[mi], b0, b1);
                        mma_f16(c, al[mi], b0, b1);
                    }
                }
            }
        }
        __syncthreads();
    }

    // ---- epilogue ----
    __half* Dh = (region == 0) ? g_Qh : (region == 1) ? g_Kh : g_Vh;
    const float QS = 1.4426950408889634f / 128.0f;

#pragma unroll
    for (int mi = 0; mi < 4; mi++) {
#pragma unroll
        for (int ni = 0; ni < 8; ni++) {
            int row0 = bm + wm + mi * 16 + (lane >> 2);
            int colL = bnl + wn + ni * 8 + (lane & 3) * 2;
            float2 bb = *(const float2*)(bias + colL);
            float f0 = acc[mi][ni][0] + bb.x, f1 = acc[mi][ni][1] + bb.y;
            float f2 = acc[mi][ni][2] + bb.x, f3 = acc[mi][ni][3] + bb.y;
            if (job == 0) {
                *(float2*)(out + (size_t)row0 * DIMM + colL)       = make_float2(f0, f1);
                *(float2*)(out + (size_t)(row0 + 8) * DIMM + colL) = make_float2(f2, f3);
            } else {
                if (region <= 1) {   // rope for Q and K
                    int i = (colL & 127) >> 1;
                    float2 cs0 = g_rt[(row0 & (SEQ - 1)) * 64 + i];
                    float2 cs1 = g_rt[((row0 + 8) & (SEQ - 1)) * 64 + i];
                    float t0 = f0 * cs0.x - f1 * cs0.y;
                    float t1 = f1 * cs0.x + f0 * cs0.y;
                    float t2 = f2 * cs1.x - f3 * cs1.y;
                    float t3 = f3 * cs1.x + f2 * cs1.y;
                    if (region == 0) { t0 *= QS; t1 *= QS; t2 *= QS; t3 *= QS; }
                    f0 = t0; f1 = t1; f2 = t2; f3 = t3;
                }
                if (region == 0) {   // Q: hi/lo split
                    uint32_t h0, l0, h1, l1;
                    split2h(f0, f1, h0, l0);
                    split2h(f2, f3, h1, l1);
                    *(uint32_t*)(g_Qh + (size_t)row0 * DIMM + colL)       = h0;
                    *(uint32_t*)(g_Ql + (size_t)row0 * DIMM + colL)       = l0;
                    *(uint32_t*)(g_Qh + (size_t)(row0 + 8) * DIMM + colL) = h1;
                    *(uint32_t*)(g_Ql + (size_t)(row0 + 8) * DIMM + colL) = l1;
                } else {             // K, V: fp16 only
                    *(uint32_t*)(Dh + (size_t)row0 * DIMM + colL)       = packh2(f0, f1);
                    *(uint32_t*)(Dh + (size_t)(row0 + 8) * DIMM + colL) = packh2(f2, f3);
                }
            }
        }
    }
}

// ---------------------------------------------------------------------------
// fp16x2 flash attention: S = (Qh+Ql) K^T (2 mma), O = (Ph+Pl) V (2 mma).
// BR=128 (8 warps x 16 rows), BC=64, d=128, 256 threads.
// smem: Qh[0:32K) Ql[32K:64K) + 2 stages of {K 16K, V 16K} = 128KB total.
// ---------------------------------------------------------------------------
#define FQH 0u
#define FQL 32768u
#define FST(s) (65536u + (uint32_t)(s) * 32768u)
#define FLASH_SMEM 131072

__device__ __forceinline__ uint32_t fswz(uint32_t row, uint32_t colbyte) {
    uint32_t off = row * 256u + colbyte;
    return off ^ ((row & 7u) << 4);
}

__device__ __forceinline__ void flash_load_kv(
    uint32_t sb, int stage, size_t kb,
    const __half* __restrict__ Kh_, const __half* __restrict__ Vh_, int tid)
{
    uint32_t base = sb + FST(stage);
#pragma unroll
    for (int c = tid; c < 1024; c += 256) {
        uint32_t row = c >> 4, ch = c & 15;
        uint32_t d = fswz(row, ch * 16);
        size_t so = kb + (size_t)row * DIMM + ch * 8;
        cp16(base + d,          Kh_ + so);
        cp16(base + 16384u + d, Vh_ + so);
    }
}

__global__ __launch_bounds__(256) void flash_tc(
    const __half* __restrict__ Qh_, const __half* __restrict__ Ql_,
    const __half* __restrict__ Kh_, const __half* __restrict__ Vh_,
    __half* __restrict__ Ah, __half* __restrict__ Al)
{
    const uint32_t sb = sm_u32(gsm);
    const int tid  = threadIdx.x;
    const int lane = tid & 31;
    const int wid  = tid >> 5;
    const int wr   = wid * 16;
    const int bh   = blockIdx.y;
    const int b    = bh >> 4;
    const int h    = bh & 15;
    const int q0   = blockIdx.x * 128;

    const size_t qg = (size_t)(b * SEQ + q0) * DIMM + h * HDIM;
    const size_t kg0 = (size_t)(b * SEQ) * DIMM + h * HDIM;

#pragma unroll
    for (int c = tid; c < 2048; c += 256) {
        uint32_t row = c >> 4, ch = c & 15;
        uint32_t d = fswz(row, ch * 16);
        size_t so = qg + (size_t)row * DIMM + ch * 8;
        cp16(sb + FQH + d, Qh_ + so);
        cp16(sb + FQL + d, Ql_ + so);
    }
    flash_load_kv(sb, 0, kg0, Kh_, Vh_, tid);
    asm volatile("cp.async.commit_group;" ::: "memory");

    float acc_o[16][4];
#pragma unroll
    for (int ni = 0; ni < 16; ni++)
#pragma unroll
        for (int e = 0; e < 4; e++) acc_o[ni][e] = 0.0f;
    float m_a = -INFINITY, m_b = -INFINITY, l_a = 0.0f, l_b = 0.0f;

    const uint32_t arow = (uint32_t)(wr + (lane & 15));
    const uint32_t chalf = (uint32_t)((lane >> 4) * 16);

    for (int kt = 0; kt < SEQ / 64; kt++) {
        asm volatile("cp.async.wait_group 0;" ::: "memory");
        __syncthreads();
        if (kt + 1 < SEQ / 64) {
            flash_load_kv(sb, (kt + 1) & 1, kg0 + (size_t)(kt + 1) * 64 * DIMM,
                          Kh_, Vh_, tid);
            asm volatile("cp.async.commit_group;" ::: "memory");
        }
        const uint32_t kbase = sb + FST(kt & 1);

        // ---- S = Q K^T (2 mma) ----
        float s[8][4];
#pragma unroll
        for (int j = 0; j < 8; j++)
#pragma unroll
            for (int e = 0; e < 4; e++) s[j][e] = 0.0f;

#pragma unroll
        for (int kc = 0; kc < 8; kc++) {
            uint32_t cb = (uint32_t)kc * 32 + chalf;
            uint32_t aq[4], aql[4];
            ldsm_x4(aq,  sb + FQH + fswz(arow, cb));
            ldsm_x4(aql, sb + FQL + fswz(arow, cb));
#pragma unroll
            for (int g = 0; g < 4; g++) {
                uint32_t krow = (uint32_t)(g * 16 + (lane & 15));
                uint32_t kh4[4];
                ldsm_x4(kh4, kbase + fswz(krow, cb));
                mma_f16(s[2 * g],     aq,  kh4[0], kh4[2]);
                mma_f16(s[2 * g],     aql, kh4[0], kh4[2]);
                mma_f16(s[2 * g + 1], aq,  kh4[1], kh4[3]);
                mma_f16(s[2 * g + 1], aql, kh4[1], kh4[3]);
            }
        }

        // ---- online softmax ----
        float mxa = -INFINITY, mxb = -INFINITY;
#pragma unroll
        for (int j = 0; j < 8; j++) {
            mxa = fmaxf(mxa, fmaxf(s[j][0], s[j][1]));
            mxb = fmaxf(mxb, fmaxf(s[j][2], s[j][3]));
        }
        mxa = fmaxf(mxa, __shfl_xor_sync(0xffffffffu, mxa, 1));
        mxa = fmaxf(mxa, __shfl_xor_sync(0xffffffffu, mxa, 2));
        mxb = fmaxf(mxb, __shfl_xor_sync(0xffffffffu, mxb, 1));
        mxb = fmaxf(mxb, __shfl_xor_sync(0xffffffffu, mxb, 2));

        float mna = fmaxf(m_a, mxa), mnb = fmaxf(m_b, mxb);
        float ca = fexp2(m_a - mna), cb2 = fexp2(m_b - mnb);
        m_a = mna; m_b = mnb;

        float sa = 0.0f, sbv = 0.0f;
        uint32_t ph[8][2], pl[8][2];
#pragma unroll
        for (int j = 0; j < 8; j++) {
            float p0 = fexp2(s[j][0] - mna);
            float p1 = fexp2(s[j][1] - mna);
            float p2 = fexp2(s[j][2] - mnb);
            float p3 = fexp2(s[j][3] - mnb);
            sa  += p0 + p1;
            sbv += p2 + p3;
            split2h(p0, p1, ph[j][0], pl[j][0]);
            split2h(p2, p3, ph[j][1], pl[j][1]);
        }
        sa  += __shfl_xor_sync(0xffffffffu, sa, 1);
        sa  += __shfl_xor_sync(0xffffffffu, sa, 2);
        sbv += __shfl_xor_sync(0xffffffffu, sbv, 1);
        sbv += __shfl_xor_sync(0xffffffffu, sbv, 2);
        l_a = l_a * ca + sa;
        l_b = l_b * cb2 + sbv;

#pragma unroll
        for (int ni = 0; ni < 16; ni++) {
            acc_o[ni][0] *= ca;  acc_o[ni][1] *= ca;
            acc_o[ni][2] *= cb2; acc_o[ni][3] *= cb2;
        }

        // ---- O += P V (2 mma) ----
        const uint32_t vb = kbase + 16384u;
#pragma unroll
        for (int kc2 = 0; kc2 < 4; kc2++) {
            uint32_t aPh[4] = {ph[2 * kc2][0], ph[2 * kc2][1],
                               ph[2 * kc2 + 1][0], ph[2 * kc2 + 1][1]};
            uint32_t aPl[4] = {pl[2 * kc2][0], pl[2 * kc2][1],
                               pl[2 * kc2 + 1][0], pl[2 * kc2 + 1][1]};
            uint32_t vrow = (uint32_t)(kc2 * 16 + (lane & 15));
#pragma unroll
            for (int nd = 0; nd < 8; nd++) {
                uint32_t cb = (uint32_t)nd * 32 + chalf;
                uint32_t vh4[4];
                ldsm_x4t(vh4, vb + fswz(vrow, cb));
                mma_f16(acc_o[2 * nd],     aPh, vh4[0], vh4[1]);
                mma_f16(acc_o[2 * nd],     aPl, vh4[0], vh4[1]);
                mma_f16(acc_o[2 * nd + 1], aPh, vh4[2], vh4[3]);
                mma_f16(acc_o[2 * nd + 1], aPl, vh4[2], vh4[3]);
            }
        }
    }

    // ---- epilogue: normalize, fp16 hi/lo split, store ----
    float inva = __fdividef(1.0f, l_a);
    float invb = __fdividef(1.0f, l_b);
    int gr = lane >> 2, c2 = (lane & 3) * 2;
    size_t oa = (size_t)(b * SEQ + q0 + wr + gr) * DIMM + h * HDIM;
    size_t ob = oa + (size_t)8 * DIMM;
#pragma unroll
    for (int ni = 0; ni < 16; ni++) {
        int col = ni * 8 + c2;
        uint32_t hA, lA, hB, lB;
        split2h(acc_o[ni][0] * inva, acc_o[ni][1] * inva, hA, lA);
        split2h(acc_o[ni][2] * invb, acc_o[ni][3] * invb, hB, lB);
        *(uint32_t*)&Ah[oa + col] = hA;
        *(uint32_t*)&Al[oa + col] = lA;
        *(uint32_t*)&Ah[ob + col] = hB;
        *(uint32_t*)&Al[ob + col] = lB;
    }
}

// ---------------------------------------------------------------------------
extern "C" void kernel_launch(void* const* d_in, const int* in_sizes, int n_in,
                              void* d_out, int out_size)
{
    const float* x  = (const float*)d_in[0];
    const float* Wq = (const float*)d_in[1];
    const float* bq = (const float*)d_in[2];
    const float* Wk = (const float*)d_in[3];
    const float* bk = (const float*)d_in[4];
    const float* Wv = (const float*)d_in[5];
    const float* bv = (const float*)d_in[6];
    const float* Wo = (const float*)d_in[7];
    const float* bo = (const float*)d_in[8];
    float* out = (float*)d_out;

    __half *xh, *xl, *w, *qh, *ql, *kh, *vh, *ah, *al;
    cudaGetSymbolAddress((void**)&xh, g_xh);
    cudaGetSymbolAddress((void**)&xl, g_xl);
    cudaGetSymbolAddress((void**)&w,  g_W);
    cudaGetSymbolAddress((void**)&qh, g_Qh);
    cudaGetSymbolAddress((void**)&ql, g_Ql);
    cudaGetSymbolAddress((void**)&kh, g_Kh);
    cudaGetSymbolAddress((void**)&vh, g_Vh);
    cudaGetSymbolAddress((void**)&ah, g_Ah);
    cudaGetSymbolAddress((void**)&al, g_Al);

    cudaFuncSetAttribute(tc3_gemm,
                         cudaFuncAttributeMaxDynamicSharedMemorySize, GM3_SMEM);
    cudaFuncSetAttribute(flash_tc,
                         cudaFuncAttributeMaxDynamicSharedMemorySize, FLASH_SMEM);

    const int NX = MTOK * DIMM;
    const int NW = DIMM * DIMM;

    split_kernel<<<NX / 4 / 256, 256>>>(x, xh, xl, NX);
    convert_kernel<<<NW / 4 / 256, 256>>>(Wq, w + 0 * WSZ, NW);
    convert_kernel<<<NW / 4 / 256, 256>>>(Wk, w + 1 * WSZ, NW);
    convert_kernel<<<NW / 4 / 256, 256>>>(Wv, w + 2 * WSZ, NW);
    convert_kernel<<<NW / 4 / 256, 256>>>(Wo, w + 3 * WSZ, NW);
    rope_table_kernel<<<(SEQ * 64) / 256, 256>>>();

    // Fused Q/K/V projection + bias + RoPE + fp16 pack
    tc3_gemm<<<dim3(3 * DIMM / 256, MTOK / 128), 256, GM3_SMEM>>>(
        xh, xl, w, bq, bk, bv, bo, nullptr, 1);

    flash_tc<<<dim3(SEQ / 128, BATCH * NHEAD), 256, FLASH_SMEM>>>(
        qh, ql, kh, vh, ah, al);

    // Output projection (fp32 + bias)
    tc3_gemm<<<dim3(DIMM / 256, MTOK / 128), 256, GM3_SMEM>>>(
        ah, al, w, bq, bk, bv, bo, out, 0);
}